// round 1
// baseline (speedup 1.0000x reference)
#include <cuda_runtime.h>
#include <math.h>

#define NATOMS 100000
#define NEDGES 1600000
#define NB 128
#define NRBF 32
#define NG 64
#define CUTOFF_F 10.0f
#define PI_F 3.14159265358979f
#define LOG2_F 0.69314718055994531f

// ---------------- scratch (static __device__, no allocations) ----------------
__device__ float g_d[NEDGES];
__device__ float g_rc[NEDGES];
__device__ float g_F[(size_t)NEDGES * NRBF];    // rbf + edge_emb[attr], 204.8MB
__device__ float g_x[(size_t)NATOMS * NB];
__device__ float g_xf[(size_t)NATOMS * NB];
__device__ float g_agg[(size_t)NATOMS * NB];
__device__ float g_t[(size_t)NATOMS * NB];

// ---------------- small math helpers ----------------
__device__ __forceinline__ float sspf(float v) {
    // softplus(v) - log(2), numerically stable
    float a = fabsf(v);
    return fmaxf(v, 0.0f) + log1pf(__expf(-a)) - LOG2_F;
}
__device__ __forceinline__ float siluf(float v) {
    return v * (1.0f / (1.0f + __expf(-v)));
}

// ---------------- utility kernels ----------------
__global__ void zero_kernel(float4* __restrict__ p, int n4) {
    int i = blockIdx.x * blockDim.x + threadIdx.x;
    if (i < n4) p[i] = make_float4(0.f, 0.f, 0.f, 0.f);
}

__global__ void edge_geom(const float* __restrict__ pos,
                          const int* __restrict__ idx_i,
                          const int* __restrict__ idx_j,
                          float* __restrict__ d, float* __restrict__ rc, int E) {
    int e = blockIdx.x * blockDim.x + threadIdx.x;
    if (e >= E) return;
    int a = idx_i[e], b = idx_j[e];
    float dx = pos[a * 3 + 0] - pos[b * 3 + 0];
    float dy = pos[a * 3 + 1] - pos[b * 3 + 1];
    float dz = pos[a * 3 + 2] - pos[b * 3 + 2];
    float dd = sqrtf(dx * dx + dy * dy + dz * dz);
    d[e] = dd;
    rc[e] = (dd < CUTOFF_F) ? 0.5f * (cosf(dd * (PI_F / CUTOFF_F)) + 1.0f) : 0.0f;
}

__global__ void edge_rbf(const int* __restrict__ edge_attr,
                         const float* __restrict__ edge_emb,
                         const float* __restrict__ d,
                         float* __restrict__ F, int E) {
    int t = blockIdx.x * blockDim.x + threadIdx.x;
    if (t >= E * NRBF) return;
    int e = t >> 5, k = t & 31;
    const float width = CUTOFF_F / 31.0f;
    const float coeff = -0.5f / (width * width);
    float u = d[e] - (float)k * width;
    F[t] = expf(coeff * u * u) + edge_emb[edge_attr[e] * NRBF + k];
}

__global__ void embed_kernel(const int* __restrict__ z, const int* __restrict__ z_res,
                             const float* __restrict__ ele_emb, const float* __restrict__ res_emb,
                             float* __restrict__ x, int N) {
    int t = blockIdx.x * blockDim.x + threadIdx.x;
    if (t >= N * NB) return;
    int n = t >> 7, c = t & 127;
    x[t] = ele_emb[z[n] * NB + c] + res_emb[z_res[n] * NB + c];
}

// ---------------- generic node GEMM: out = [res +] post( pre(in) @ W + bias ) ----------------
// M x 128 @ 128 x 128. Block: 256 thr, tile 64 rows x 128 cols, per-thread 4x8.
template <int PRE, int POST, int RES>
__global__ __launch_bounds__(256) void node_gemm(
    const float* __restrict__ in, const float* __restrict__ W,
    const float* __restrict__ bias, const float* __restrict__ res,
    float* __restrict__ out, int M)
{
    extern __shared__ float sm[];
    float* sIn = sm;            // 64*128
    float* sW  = sm + 64 * 128; // 128*128
    const int t = threadIdx.x;
    const int tx = t & 15, ty = t >> 4;
    const int m0 = blockIdx.x * 64;

#pragma unroll
    for (int i = 0; i < 16; i++) {
        int idx = (i * 256 + t) * 4;
        *(float4*)&sW[idx] = *(const float4*)&W[idx];
    }
#pragma unroll
    for (int i = 0; i < 8; i++) {
        int idx = (i * 256 + t) * 4;
        int row = idx >> 7;
        float4 v = make_float4(0.f, 0.f, 0.f, 0.f);
        if (m0 + row < M) v = *(const float4*)&in[(size_t)(m0 + row) * NB + (idx & 127)];
        if (PRE == 1) { v.x = siluf(v.x); v.y = siluf(v.y); v.z = siluf(v.z); v.w = siluf(v.w); }
        *(float4*)&sIn[idx] = v;
    }
    __syncthreads();

    float acc[4][8];
#pragma unroll
    for (int i = 0; i < 4; i++)
#pragma unroll
        for (int j = 0; j < 8; j++) acc[i][j] = 0.f;

#pragma unroll 2
    for (int k = 0; k < 128; k += 4) {
        float a[4][4];
#pragma unroll
        for (int i = 0; i < 4; i++) {
            float4 v = *(const float4*)&sIn[(ty * 4 + i) * 128 + k];
            a[i][0] = v.x; a[i][1] = v.y; a[i][2] = v.z; a[i][3] = v.w;
        }
#pragma unroll
        for (int kk = 0; kk < 4; kk++) {
            float4 b0 = *(const float4*)&sW[(k + kk) * 128 + tx * 8];
            float4 b1 = *(const float4*)&sW[(k + kk) * 128 + tx * 8 + 4];
            float b[8] = { b0.x, b0.y, b0.z, b0.w, b1.x, b1.y, b1.z, b1.w };
#pragma unroll
            for (int i = 0; i < 4; i++)
#pragma unroll
                for (int j = 0; j < 8; j++)
                    acc[i][j] = fmaf(a[i][kk], b[j], acc[i][j]);
        }
    }

    float bb[8];
#pragma unroll
    for (int j = 0; j < 8; j++) bb[j] = bias ? bias[tx * 8 + j] : 0.f;

#pragma unroll
    for (int i = 0; i < 4; i++) {
        int m = m0 + ty * 4 + i;
        if (m < M) {
#pragma unroll
            for (int j = 0; j < 8; j++) {
                float v = acc[i][j] + bb[j];
                if (POST == 1) v = sspf(v);
                if (RES == 1) v += res[(size_t)m * NB + tx * 8 + j];
                out[(size_t)m * NB + tx * 8 + j] = v;
            }
        }
    }
}

// ---------------- fused edge kernel ----------------
// per block: 128 edges. h = ssp(F@W1+b1); Wij = (h@W2+b2)*rcut;
// agg[idx_i] += xf[idx_j] * Wij   (atomics, L2-resident)
__global__ __launch_bounds__(256) void edge_kernel(
    const int* __restrict__ idx_i, const int* __restrict__ idx_j,
    const float* __restrict__ W1, const float* __restrict__ b1,
    const float* __restrict__ W2, const float* __restrict__ b2,
    const float* __restrict__ Ff, const float* __restrict__ rcut,
    const float* __restrict__ xf, float* __restrict__ agg, int E)
{
    extern __shared__ float sm[];
    float* sF  = sm;           // 128*32  = 4096
    float* sW1 = sm + 4096;    // 32*128  = 4096
    float* sH  = sm + 8192;    // 128*128 = 16384
    float* sW2 = sm + 24576;   // 128*128 = 16384
    float* sB1 = sm + 40960;   // 128
    float* sB2 = sm + 41088;   // 128

    const int t = threadIdx.x;
    const int tx = t & 15, ty = t >> 4;
    const int eb = blockIdx.x * 128;

#pragma unroll
    for (int i = 0; i < 4; i++) {
        int idx = (i * 256 + t) * 4;
        *(float4*)&sW1[idx] = *(const float4*)&W1[idx];
    }
#pragma unroll
    for (int i = 0; i < 16; i++) {
        int idx = (i * 256 + t) * 4;
        *(float4*)&sW2[idx] = *(const float4*)&W2[idx];
    }
    if (t < 128) { sB1[t] = b1[t]; sB2[t] = b2[t]; }
#pragma unroll
    for (int i = 0; i < 4; i++) {
        int idx = (i * 256 + t) * 4;
        int row = idx >> 5;
        float4 v = make_float4(0.f, 0.f, 0.f, 0.f);
        if (eb + row < E) v = *(const float4*)&Ff[(size_t)(eb + row) * NRBF + (idx & 31)];
        *(float4*)&sF[idx] = v;
    }
    __syncthreads();

    float acc[8][8];
#pragma unroll
    for (int i = 0; i < 8; i++)
#pragma unroll
        for (int j = 0; j < 8; j++) acc[i][j] = 0.f;

    // phase 1: [128,32] @ [32,128]
#pragma unroll
    for (int k = 0; k < 32; k += 4) {
        float a[8][4];
#pragma unroll
        for (int i = 0; i < 8; i++) {
            float4 v = *(const float4*)&sF[(ty * 8 + i) * 32 + k];
            a[i][0] = v.x; a[i][1] = v.y; a[i][2] = v.z; a[i][3] = v.w;
        }
#pragma unroll
        for (int kk = 0; kk < 4; kk++) {
            float4 b0 = *(const float4*)&sW1[(k + kk) * 128 + tx * 8];
            float4 b1v = *(const float4*)&sW1[(k + kk) * 128 + tx * 8 + 4];
            float b[8] = { b0.x, b0.y, b0.z, b0.w, b1v.x, b1v.y, b1v.z, b1v.w };
#pragma unroll
            for (int i = 0; i < 8; i++)
#pragma unroll
                for (int j = 0; j < 8; j++)
                    acc[i][j] = fmaf(a[i][kk], b[j], acc[i][j]);
        }
    }
    // ssp + bias -> shared h
#pragma unroll
    for (int i = 0; i < 8; i++)
#pragma unroll
        for (int j = 0; j < 8; j++)
            sH[(ty * 8 + i) * 128 + tx * 8 + j] = sspf(acc[i][j] + sB1[tx * 8 + j]);
    __syncthreads();

#pragma unroll
    for (int i = 0; i < 8; i++)
#pragma unroll
        for (int j = 0; j < 8; j++) acc[i][j] = 0.f;

    // phase 2: [128,128] @ [128,128]
#pragma unroll 2
    for (int k = 0; k < 128; k += 4) {
        float a[8][4];
#pragma unroll
        for (int i = 0; i < 8; i++) {
            float4 v = *(const float4*)&sH[(ty * 8 + i) * 128 + k];
            a[i][0] = v.x; a[i][1] = v.y; a[i][2] = v.z; a[i][3] = v.w;
        }
#pragma unroll
        for (int kk = 0; kk < 4; kk++) {
            float4 b0 = *(const float4*)&sW2[(k + kk) * 128 + tx * 8];
            float4 b1v = *(const float4*)&sW2[(k + kk) * 128 + tx * 8 + 4];
            float b[8] = { b0.x, b0.y, b0.z, b0.w, b1v.x, b1v.y, b1v.z, b1v.w };
#pragma unroll
            for (int i = 0; i < 8; i++)
#pragma unroll
                for (int j = 0; j < 8; j++)
                    acc[i][j] = fmaf(a[i][kk], b[j], acc[i][j]);
        }
    }

    float bb[8];
#pragma unroll
    for (int j = 0; j < 8; j++) bb[j] = sB2[tx * 8 + j];

    // epilogue: scale by rcut, gather xf[idx_j], scatter-add into agg[idx_i]
#pragma unroll
    for (int i = 0; i < 8; i++) {
        int e = eb + ty * 8 + i;
        if (e < E) {
            float rc = rcut[e];
            int ii = idx_i[e], jj = idx_j[e];
            const float4* xp = (const float4*)&xf[(size_t)jj * NB + tx * 8];
            float4 x0 = xp[0], x1 = xp[1];
            float* ag = &agg[(size_t)ii * NB + tx * 8];
            atomicAdd(ag + 0, (acc[i][0] + bb[0]) * rc * x0.x);
            atomicAdd(ag + 1, (acc[i][1] + bb[1]) * rc * x0.y);
            atomicAdd(ag + 2, (acc[i][2] + bb[2]) * rc * x0.z);
            atomicAdd(ag + 3, (acc[i][3] + bb[3]) * rc * x0.w);
            atomicAdd(ag + 4, (acc[i][4] + bb[4]) * rc * x1.x);
            atomicAdd(ag + 5, (acc[i][5] + bb[5]) * rc * x1.y);
            atomicAdd(ag + 6, (acc[i][6] + bb[6]) * rc * x1.z);
            atomicAdd(ag + 7, (acc[i][7] + bb[7]) * rc * x1.w);
        }
    }
}

// ---------------- head ----------------
__global__ void norm_kernel(const float* __restrict__ x, float* __restrict__ o, int M) {
    int w = (blockIdx.x * blockDim.x + threadIdx.x) >> 5;
    int lane = threadIdx.x & 31;
    if (w >= M) return;
    float4 v = ((const float4*)(x + (size_t)w * NB))[lane];
    float s = v.x * v.x + v.y * v.y + v.z * v.z + v.w * v.w;
#pragma unroll
    for (int o2 = 16; o2 > 0; o2 >>= 1) s += __shfl_xor_sync(0xffffffffu, s, o2);
    float scale = 1.0f / fmaxf(sqrtf(s), 1e-12f);
    ((float4*)(o + (size_t)w * NB))[lane] =
        make_float4(v.x * scale, v.y * scale, v.z * scale, v.w * scale);
}

__global__ void head_final(const float* __restrict__ h, const float* __restrict__ w2,
                           const int* __restrict__ batch, float* __restrict__ out, int M) {
    int w = (blockIdx.x * blockDim.x + threadIdx.x) >> 5;
    int lane = threadIdx.x & 31;
    if (w >= M) return;
    float4 v = ((const float4*)(h + (size_t)w * NB))[lane];
    float4 ww = ((const float4*)w2)[lane];
    float s = siluf(v.x) * ww.x + siluf(v.y) * ww.y + siluf(v.z) * ww.z + siluf(v.w) * ww.w;
#pragma unroll
    for (int o2 = 16; o2 > 0; o2 >>= 1) s += __shfl_xor_sync(0xffffffffu, s, o2);
    if (lane == 0) atomicAdd(&out[batch[w]], s);
}

// ---------------- launch ----------------
extern "C" void kernel_launch(void* const* d_in, const int* in_sizes, int n_in,
                              void* d_out, int out_size)
{
    const int*   z         = (const int*)d_in[0];
    const int*   z_res     = (const int*)d_in[1];
    const float* pos       = (const float*)d_in[2];
    const int*   idx_i     = (const int*)d_in[3];
    const int*   idx_j     = (const int*)d_in[4];
    const int*   edge_attr = (const int*)d_in[5];
    const int*   batch     = (const int*)d_in[6];
    const float* ele_emb   = (const float*)d_in[7];
    const float* res_emb   = (const float*)d_in[8];
    const float* edge_emb  = (const float*)d_in[9];
    const float* in2f_W    = (const float*)d_in[10];
    const float* filt_W1   = (const float*)d_in[11];
    const float* filt_b1   = (const float*)d_in[12];
    const float* filt_W2   = (const float*)d_in[13];
    const float* filt_b2   = (const float*)d_in[14];
    const float* f2out_W1  = (const float*)d_in[15];
    const float* f2out_b1  = (const float*)d_in[16];
    const float* f2out_W2  = (const float*)d_in[17];
    const float* f2out_b2  = (const float*)d_in[18];
    const float* head_W1   = (const float*)d_in[19];
    const float* head_b1   = (const float*)d_in[20];
    const float* head_W2   = (const float*)d_in[21];
    float* out = (float*)d_out;

    const int N = in_sizes[0];
    const int E = in_sizes[3];

    float *pD, *pRc, *pF, *pX, *pXf, *pAgg, *pT;
    cudaGetSymbolAddress((void**)&pD, g_d);
    cudaGetSymbolAddress((void**)&pRc, g_rc);
    cudaGetSymbolAddress((void**)&pF, g_F);
    cudaGetSymbolAddress((void**)&pX, g_x);
    cudaGetSymbolAddress((void**)&pXf, g_xf);
    cudaGetSymbolAddress((void**)&pAgg, g_agg);
    cudaGetSymbolAddress((void**)&pT, g_t);

    const int GEMM_SMEM = (64 * 128 + 128 * 128) * 4;             // 98304
    const int EDGE_SMEM = (4096 + 4096 + 16384 + 16384 + 256) * 4; // 164864
    cudaFuncSetAttribute(node_gemm<0,0,0>, cudaFuncAttributeMaxDynamicSharedMemorySize, GEMM_SMEM);
    cudaFuncSetAttribute(node_gemm<0,1,0>, cudaFuncAttributeMaxDynamicSharedMemorySize, GEMM_SMEM);
    cudaFuncSetAttribute(node_gemm<0,0,1>, cudaFuncAttributeMaxDynamicSharedMemorySize, GEMM_SMEM);
    cudaFuncSetAttribute(node_gemm<1,0,0>, cudaFuncAttributeMaxDynamicSharedMemorySize, GEMM_SMEM);
    cudaFuncSetAttribute(edge_kernel, cudaFuncAttributeMaxDynamicSharedMemorySize, EDGE_SMEM);

    // init
    zero_kernel<<<1, 64>>>((float4*)out, out_size / 4);
    edge_geom<<<(E + 255) / 256, 256>>>(pos, idx_i, idx_j, pD, pRc, E);
    edge_rbf<<<(E * NRBF + 255) / 256, 256>>>(edge_attr, edge_emb, pD, pF, E);
    embed_kernel<<<(N * NB + 255) / 256, 256>>>(z, z_res, ele_emb, res_emb, pX, N);

    const int gblocks = (N + 63) / 64;
    const int eblocks = (E + 127) / 128;
    const int nz4 = N * NB / 4;

    for (int it = 0; it < 6; it++) {
        node_gemm<0,0,0><<<gblocks, 256, GEMM_SMEM>>>(
            pX, in2f_W + (size_t)it * NB * NB, nullptr, nullptr, pXf, N);
        zero_kernel<<<(nz4 + 255) / 256, 256>>>((float4*)pAgg, nz4);
        edge_kernel<<<eblocks, 256, EDGE_SMEM>>>(
            idx_i, idx_j,
            filt_W1 + (size_t)it * NRBF * NB, filt_b1 + (size_t)it * NB,
            filt_W2 + (size_t)it * NB * NB,  filt_b2 + (size_t)it * NB,
            pF, pRc, pXf, pAgg, E);
        node_gemm<0,1,0><<<gblocks, 256, GEMM_SMEM>>>(
            pAgg, f2out_W1 + (size_t)it * NB * NB, f2out_b1 + (size_t)it * NB, nullptr, pT, N);
        node_gemm<0,0,1><<<gblocks, 256, GEMM_SMEM>>>(
            pT, f2out_W2 + (size_t)it * NB * NB, f2out_b2 + (size_t)it * NB, pX, pX, N);
    }

    norm_kernel<<<(N + 7) / 8, 256>>>(pX, pT, N);
    node_gemm<1,0,0><<<gblocks, 256, GEMM_SMEM>>>(pT, head_W1, head_b1, nullptr, pXf, N);
    head_final<<<(N + 7) / 8, 256>>>(pXf, head_W2, batch, out, N);
}

// round 2
// speedup vs baseline: 1.3158x; 1.3158x over previous
#include <cuda_runtime.h>
#include <math.h>

#define NATOMS 100000
#define NEDGES 1600000
#define NB 128
#define NRBF 32
#define CUTOFF_F 10.0f
#define PI_F 3.14159265358979f
#define LOG2_F 0.69314718055994531f

// ---------------- scratch (static __device__, no allocations) ----------------
__device__ float g_d[NEDGES];
__device__ float g_rc[NEDGES];
__device__ float g_F[(size_t)NEDGES * NRBF];
__device__ float g_x[(size_t)NATOMS * NB];
__device__ float g_xf[(size_t)NATOMS * NB];
__device__ float g_agg[(size_t)NATOMS * NB];
__device__ float g_t[(size_t)NATOMS * NB];

// ---------------- helpers ----------------
__device__ __forceinline__ float sspf(float v) {
    float a = fabsf(v);
    return fmaxf(v, 0.0f) + log1pf(__expf(-a)) - LOG2_F;
}
__device__ __forceinline__ float siluf(float v) {
    return v * (1.0f / (1.0f + __expf(-v)));
}
__device__ __forceinline__ void red_add_v4(float* p, float a, float b, float c, float d) {
    asm volatile("red.global.add.v4.f32 [%0], {%1,%2,%3,%4};"
                 :: "l"(p), "f"(a), "f"(b), "f"(c), "f"(d) : "memory");
}

// ---------------- utility kernels ----------------
__global__ void zero_kernel(float4* __restrict__ p, int n4) {
    int i = blockIdx.x * blockDim.x + threadIdx.x;
    if (i < n4) p[i] = make_float4(0.f, 0.f, 0.f, 0.f);
}

__global__ void edge_geom(const float* __restrict__ pos,
                          const int* __restrict__ idx_i,
                          const int* __restrict__ idx_j,
                          float* __restrict__ d, float* __restrict__ rc, int E) {
    int e = blockIdx.x * blockDim.x + threadIdx.x;
    if (e >= E) return;
    int a = idx_i[e], b = idx_j[e];
    float dx = pos[a * 3 + 0] - pos[b * 3 + 0];
    float dy = pos[a * 3 + 1] - pos[b * 3 + 1];
    float dz = pos[a * 3 + 2] - pos[b * 3 + 2];
    float dd = sqrtf(dx * dx + dy * dy + dz * dz);
    d[e] = dd;
    rc[e] = (dd < CUTOFF_F) ? 0.5f * (cosf(dd * (PI_F / CUTOFF_F)) + 1.0f) : 0.0f;
}

__global__ void edge_rbf(const int* __restrict__ edge_attr,
                         const float* __restrict__ edge_emb,
                         const float* __restrict__ d,
                         float* __restrict__ F, int E) {
    int t = blockIdx.x * blockDim.x + threadIdx.x;
    if (t >= E * NRBF) return;
    int e = t >> 5, k = t & 31;
    const float width = CUTOFF_F / 31.0f;
    const float coeff = -0.5f / (width * width);
    float u = d[e] - (float)k * width;
    F[t] = expf(coeff * u * u) + edge_emb[edge_attr[e] * NRBF + k];
}

// embed + zero agg + zero out, one launch
__global__ void embed_zero(const int* __restrict__ z, const int* __restrict__ z_res,
                           const float* __restrict__ ele_emb, const float* __restrict__ res_emb,
                           float* __restrict__ x, float* __restrict__ agg,
                           float* __restrict__ outbuf, int N, int out_n) {
    int t = blockIdx.x * blockDim.x + threadIdx.x;
    if (t < out_n) outbuf[t] = 0.f;
    if (t >= N * NB) return;
    int n = t >> 7, c = t & 127;
    agg[t] = 0.f;
    x[t] = ele_emb[z[n] * NB + c] + res_emb[z_res[n] * NB + c];
}

// ---------------- node GEMM: out = [res +] post( pre(in) @ W + bias ) ----------------
template <int PRE, int POST, int RES>
__global__ __launch_bounds__(256) void node_gemm(
    const float* __restrict__ in, const float* __restrict__ W,
    const float* __restrict__ bias, const float* __restrict__ res,
    float* __restrict__ out, int M)
{
    extern __shared__ float sm[];
    float* sIn = sm;            // 64*128
    float* sW  = sm + 64 * 128; // 128*128
    const int t = threadIdx.x;
    const int tx = t & 15, ty = t >> 4;
    const int m0 = blockIdx.x * 64;

#pragma unroll
    for (int i = 0; i < 16; i++) {
        int idx = (i * 256 + t) * 4;
        *(float4*)&sW[idx] = *(const float4*)&W[idx];
    }
#pragma unroll
    for (int i = 0; i < 8; i++) {
        int idx = (i * 256 + t) * 4;
        int row = idx >> 7;
        float4 v = make_float4(0.f, 0.f, 0.f, 0.f);
        if (m0 + row < M) v = *(const float4*)&in[(size_t)(m0 + row) * NB + (idx & 127)];
        if (PRE == 1) { v.x = siluf(v.x); v.y = siluf(v.y); v.z = siluf(v.z); v.w = siluf(v.w); }
        *(float4*)&sIn[idx] = v;
    }
    __syncthreads();

    float acc[4][8];
#pragma unroll
    for (int i = 0; i < 4; i++)
#pragma unroll
        for (int j = 0; j < 8; j++) acc[i][j] = 0.f;

#pragma unroll 2
    for (int k = 0; k < 128; k += 4) {
        float a[4][4];
#pragma unroll
        for (int i = 0; i < 4; i++) {
            float4 v = *(const float4*)&sIn[(ty * 4 + i) * 128 + k];
            a[i][0] = v.x; a[i][1] = v.y; a[i][2] = v.z; a[i][3] = v.w;
        }
#pragma unroll
        for (int kk = 0; kk < 4; kk++) {
            float4 b0 = *(const float4*)&sW[(k + kk) * 128 + tx * 8];
            float4 b1 = *(const float4*)&sW[(k + kk) * 128 + tx * 8 + 4];
            float b[8] = { b0.x, b0.y, b0.z, b0.w, b1.x, b1.y, b1.z, b1.w };
#pragma unroll
            for (int i = 0; i < 4; i++)
#pragma unroll
                for (int j = 0; j < 8; j++)
                    acc[i][j] = fmaf(a[i][kk], b[j], acc[i][j]);
        }
    }

    float bb[8];
#pragma unroll
    for (int j = 0; j < 8; j++) bb[j] = bias ? bias[tx * 8 + j] : 0.f;

#pragma unroll
    for (int i = 0; i < 4; i++) {
        int m = m0 + ty * 4 + i;
        if (m < M) {
#pragma unroll
            for (int j = 0; j < 8; j++) {
                float v = acc[i][j] + bb[j];
                if (POST == 1) v = sspf(v);
                if (RES == 1) v += res[(size_t)m * NB + tx * 8 + j];
                out[(size_t)m * NB + tx * 8 + j] = v;
            }
        }
    }
}

// ---------------- fused edge kernel ----------------
// 512 threads, tile = 128 edges x 128 filters, per-thread 8 rows x 4 cols.
// Warp = one row-group (tx = lane): a-loads broadcast, b-loads conflict-free.
__global__ __launch_bounds__(512) void edge_kernel(
    const int* __restrict__ idx_i, const int* __restrict__ idx_j,
    const float* __restrict__ W1, const float* __restrict__ b1,
    const float* __restrict__ W2, const float* __restrict__ b2,
    const float* __restrict__ Ff, const float* __restrict__ rcut,
    const float* __restrict__ xf, float* __restrict__ agg, int E)
{
    extern __shared__ float sm[];
    float* sF  = sm;           // 128*32  = 4096
    float* sW1 = sm + 4096;    // 32*128  = 4096
    float* sH  = sm + 8192;    // 128*128 = 16384
    float* sW2 = sm + 24576;   // 128*128 = 16384
    float* sB1 = sm + 40960;   // 128
    float* sB2 = sm + 41088;   // 128

    const int t = threadIdx.x;
    const int tx = t & 31;     // col group: 4 cols
    const int ty = t >> 5;     // row group: 8 rows
    const int eb = blockIdx.x * 128;

#pragma unroll
    for (int i = 0; i < 2; i++) {
        int idx = (i * 512 + t) * 4;
        *(float4*)&sW1[idx] = *(const float4*)&W1[idx];
    }
#pragma unroll
    for (int i = 0; i < 8; i++) {
        int idx = (i * 512 + t) * 4;
        *(float4*)&sW2[idx] = *(const float4*)&W2[idx];
    }
    if (t < 128) { sB1[t] = b1[t]; sB2[t] = b2[t]; }
#pragma unroll
    for (int i = 0; i < 2; i++) {
        int idx = (i * 512 + t) * 4;
        int row = idx >> 5;
        float4 v = make_float4(0.f, 0.f, 0.f, 0.f);
        if (eb + row < E) v = *(const float4*)&Ff[(size_t)(eb + row) * NRBF + (idx & 31)];
        *(float4*)&sF[idx] = v;
    }
    __syncthreads();

    float acc[8][4];
#pragma unroll
    for (int i = 0; i < 8; i++)
#pragma unroll
        for (int j = 0; j < 4; j++) acc[i][j] = 0.f;

    // phase 1: [128,32] @ [32,128]
#pragma unroll
    for (int k = 0; k < 32; k += 4) {
        float a[8][4];
#pragma unroll
        for (int i = 0; i < 8; i++) {
            float4 v = *(const float4*)&sF[(ty * 8 + i) * 32 + k];
            a[i][0] = v.x; a[i][1] = v.y; a[i][2] = v.z; a[i][3] = v.w;
        }
#pragma unroll
        for (int kk = 0; kk < 4; kk++) {
            float4 bv = *(const float4*)&sW1[(k + kk) * 128 + tx * 4];
            float b[4] = { bv.x, bv.y, bv.z, bv.w };
#pragma unroll
            for (int i = 0; i < 8; i++)
#pragma unroll
                for (int j = 0; j < 4; j++)
                    acc[i][j] = fmaf(a[i][kk], b[j], acc[i][j]);
        }
    }
    // ssp + bias -> shared h (one float4 store per row)
    {
        float bb1[4];
#pragma unroll
        for (int j = 0; j < 4; j++) bb1[j] = sB1[tx * 4 + j];
#pragma unroll
        for (int i = 0; i < 8; i++) {
            float4 h;
            h.x = sspf(acc[i][0] + bb1[0]);
            h.y = sspf(acc[i][1] + bb1[1]);
            h.z = sspf(acc[i][2] + bb1[2]);
            h.w = sspf(acc[i][3] + bb1[3]);
            *(float4*)&sH[(ty * 8 + i) * 128 + tx * 4] = h;
        }
    }
    __syncthreads();

#pragma unroll
    for (int i = 0; i < 8; i++)
#pragma unroll
        for (int j = 0; j < 4; j++) acc[i][j] = 0.f;

    // phase 2: [128,128] @ [128,128]
#pragma unroll 2
    for (int k = 0; k < 128; k += 4) {
        float a[8][4];
#pragma unroll
        for (int i = 0; i < 8; i++) {
            float4 v = *(const float4*)&sH[(ty * 8 + i) * 128 + k];
            a[i][0] = v.x; a[i][1] = v.y; a[i][2] = v.z; a[i][3] = v.w;
        }
#pragma unroll
        for (int kk = 0; kk < 4; kk++) {
            float4 bv = *(const float4*)&sW2[(k + kk) * 128 + tx * 4];
            float b[4] = { bv.x, bv.y, bv.z, bv.w };
#pragma unroll
            for (int i = 0; i < 8; i++)
#pragma unroll
                for (int j = 0; j < 4; j++)
                    acc[i][j] = fmaf(a[i][kk], b[j], acc[i][j]);
        }
    }

    float bb[4];
#pragma unroll
    for (int j = 0; j < 4; j++) bb[j] = sB2[tx * 4 + j];

    // epilogue: *rcut, gather xf[idx_j], vector-red into agg[idx_i]
#pragma unroll
    for (int i = 0; i < 8; i++) {
        int e = eb + ty * 8 + i;
        if (e < E) {
            float rc = rcut[e];
            int ii = idx_i[e], jj = idx_j[e];
            float4 xv = *(const float4*)&xf[(size_t)jj * NB + tx * 4];
            float v0 = (acc[i][0] + bb[0]) * rc * xv.x;
            float v1 = (acc[i][1] + bb[1]) * rc * xv.y;
            float v2 = (acc[i][2] + bb[2]) * rc * xv.z;
            float v3 = (acc[i][3] + bb[3]) * rc * xv.w;
            red_add_v4(&agg[(size_t)ii * NB + tx * 4], v0, v1, v2, v3);
        }
    }
}

// ---------------- head ----------------
__global__ void norm_kernel(const float* __restrict__ x, float* __restrict__ o, int M) {
    int w = (blockIdx.x * blockDim.x + threadIdx.x) >> 5;
    int lane = threadIdx.x & 31;
    if (w >= M) return;
    float4 v = ((const float4*)(x + (size_t)w * NB))[lane];
    float s = v.x * v.x + v.y * v.y + v.z * v.z + v.w * v.w;
#pragma unroll
    for (int o2 = 16; o2 > 0; o2 >>= 1) s += __shfl_xor_sync(0xffffffffu, s, o2);
    float scale = 1.0f / fmaxf(sqrtf(s), 1e-12f);
    ((float4*)(o + (size_t)w * NB))[lane] =
        make_float4(v.x * scale, v.y * scale, v.z * scale, v.w * scale);
}

__global__ void head_final(const float* __restrict__ h, const float* __restrict__ w2,
                           const int* __restrict__ batch, float* __restrict__ out, int M) {
    int w = (blockIdx.x * blockDim.x + threadIdx.x) >> 5;
    int lane = threadIdx.x & 31;
    if (w >= M) return;
    float4 v = ((const float4*)(h + (size_t)w * NB))[lane];
    float4 ww = ((const float4*)w2)[lane];
    float s = siluf(v.x) * ww.x + siluf(v.y) * ww.y + siluf(v.z) * ww.z + siluf(v.w) * ww.w;
#pragma unroll
    for (int o2 = 16; o2 > 0; o2 >>= 1) s += __shfl_xor_sync(0xffffffffu, s, o2);
    if (lane == 0) atomicAdd(&out[batch[w]], s);
}

// ---------------- launch ----------------
extern "C" void kernel_launch(void* const* d_in, const int* in_sizes, int n_in,
                              void* d_out, int out_size)
{
    const int*   z         = (const int*)d_in[0];
    const int*   z_res     = (const int*)d_in[1];
    const float* pos       = (const float*)d_in[2];
    const int*   idx_i     = (const int*)d_in[3];
    const int*   idx_j     = (const int*)d_in[4];
    const int*   edge_attr = (const int*)d_in[5];
    const int*   batch     = (const int*)d_in[6];
    const float* ele_emb   = (const float*)d_in[7];
    const float* res_emb   = (const float*)d_in[8];
    const float* edge_emb  = (const float*)d_in[9];
    const float* in2f_W    = (const float*)d_in[10];
    const float* filt_W1   = (const float*)d_in[11];
    const float* filt_b1   = (const float*)d_in[12];
    const float* filt_W2   = (const float*)d_in[13];
    const float* filt_b2   = (const float*)d_in[14];
    const float* f2out_W1  = (const float*)d_in[15];
    const float* f2out_b1  = (const float*)d_in[16];
    const float* f2out_W2  = (const float*)d_in[17];
    const float* f2out_b2  = (const float*)d_in[18];
    const float* head_W1   = (const float*)d_in[19];
    const float* head_b1   = (const float*)d_in[20];
    const float* head_W2   = (const float*)d_in[21];
    float* out = (float*)d_out;

    const int N = in_sizes[0];
    const int E = in_sizes[3];

    float *pD, *pRc, *pF, *pX, *pXf, *pAgg, *pT;
    cudaGetSymbolAddress((void**)&pD, g_d);
    cudaGetSymbolAddress((void**)&pRc, g_rc);
    cudaGetSymbolAddress((void**)&pF, g_F);
    cudaGetSymbolAddress((void**)&pX, g_x);
    cudaGetSymbolAddress((void**)&pXf, g_xf);
    cudaGetSymbolAddress((void**)&pAgg, g_agg);
    cudaGetSymbolAddress((void**)&pT, g_t);

    const int GEMM_SMEM = (64 * 128 + 128 * 128) * 4;              // 98304
    const int EDGE_SMEM = (4096 + 4096 + 16384 + 16384 + 256) * 4; // 164864
    cudaFuncSetAttribute(node_gemm<0,0,0>, cudaFuncAttributeMaxDynamicSharedMemorySize, GEMM_SMEM);
    cudaFuncSetAttribute(node_gemm<0,1,0>, cudaFuncAttributeMaxDynamicSharedMemorySize, GEMM_SMEM);
    cudaFuncSetAttribute(node_gemm<0,0,1>, cudaFuncAttributeMaxDynamicSharedMemorySize, GEMM_SMEM);
    cudaFuncSetAttribute(node_gemm<1,0,0>, cudaFuncAttributeMaxDynamicSharedMemorySize, GEMM_SMEM);
    cudaFuncSetAttribute(edge_kernel, cudaFuncAttributeMaxDynamicSharedMemorySize, EDGE_SMEM);

    edge_geom<<<(E + 255) / 256, 256>>>(pos, idx_i, idx_j, pD, pRc, E);
    edge_rbf<<<(E * NRBF + 255) / 256, 256>>>(edge_attr, edge_emb, pD, pF, E);
    embed_zero<<<(N * NB + 255) / 256, 256>>>(z, z_res, ele_emb, res_emb, pX, pAgg, out, N, out_size);

    const int gblocks = (N + 63) / 64;
    const int eblocks = (E + 127) / 128;
    const int nz4 = N * NB / 4;

    for (int it = 0; it < 6; it++) {
        if (it > 0)
            zero_kernel<<<(nz4 + 255) / 256, 256>>>((float4*)pAgg, nz4);
        node_gemm<0,0,0><<<gblocks, 256, GEMM_SMEM>>>(
            pX, in2f_W + (size_t)it * NB * NB, nullptr, nullptr, pXf, N);
        edge_kernel<<<eblocks, 512, EDGE_SMEM>>>(
            idx_i, idx_j,
            filt_W1 + (size_t)it * NRBF * NB, filt_b1 + (size_t)it * NB,
            filt_W2 + (size_t)it * NB * NB,  filt_b2 + (size_t)it * NB,
            pF, pRc, pXf, pAgg, E);
        node_gemm<0,1,0><<<gblocks, 256, GEMM_SMEM>>>(
            pAgg, f2out_W1 + (size_t)it * NB * NB, f2out_b1 + (size_t)it * NB, nullptr, pT, N);
        node_gemm<0,0,1><<<gblocks, 256, GEMM_SMEM>>>(
            pT, f2out_W2 + (size_t)it * NB * NB, f2out_b2 + (size_t)it * NB, pX, pX, N);
    }

    norm_kernel<<<(N + 7) / 8, 256>>>(pX, pT, N);
    node_gemm<1,0,0><<<gblocks, 256, GEMM_SMEM>>>(pT, head_W1, head_b1, nullptr, pXf, N);
    head_final<<<(N + 7) / 8, 256>>>(pXf, head_W2, batch, out, N);
}

// round 5
// speedup vs baseline: 1.5253x; 1.1592x over previous
#include <cuda_runtime.h>
#include <cuda_bf16.h>
#include <stdint.h>
#include <math.h>

#define NATOMS 100000
#define NEDGES 1600000
#define NB 128
#define NRBF 32
#define CUTOFF_F 10.0f
#define PI_F 3.14159265358979f
#define LOG2_F 0.69314718055994531f

// ---------------- scratch (static __device__, no allocations) ----------------
__device__ float g_d[NEDGES];
__device__ float g_rc[NEDGES];
__device__ float g_F[(size_t)NEDGES * NRBF];
__device__ float g_x[(size_t)NATOMS * NB];
__device__ float g_xf[(size_t)NATOMS * NB];
__device__ float g_agg[(size_t)NATOMS * NB];
__device__ float g_t[(size_t)NATOMS * NB];

// ---------------- math helpers ----------------
__device__ __forceinline__ float sspf(float v) {
    float a = fabsf(v);
    return fmaxf(v, 0.0f) + log1pf(__expf(-a)) - LOG2_F;
}

__device__ __forceinline__ float siluf(float v) {
    return v * (1.0f / (1.0f + __expf(-v)));
}

__device__ __forceinline__ void red_add_v2(float* p, float a, float b) {
    asm volatile("red.global.add.v2.f32 [%0], {%1,%2};"
                 :: "l"(p), "f"(a), "f"(b) : "memory");
}

// HMMA bf16: D(f32) += A(16x16 bf16) * B(16x8 bf16)
__device__ __forceinline__ void mma_bf16(float* c, const uint32_t* a, const uint32_t* b) {
    asm volatile(
        "mma.sync.aligned.m16n8k16.row.col.f32.bf16.bf16.f32 "
        "{%0,%1,%2,%3}, {%4,%5,%6,%7}, {%8,%9}, {%0,%1,%2,%3};"
        : "+f"(c[0]), "+f"(c[1]), "+f"(c[2]), "+f"(c[3])
        : "r"(a[0]), "r"(a[1]), "r"(a[2]), "r"(a[3]), "r"(b[0]), "r"(b[1]));
}

// ---------------- smem byte offsets for edge kernel ----------------
// H and W2t stored bf16 with row stride 136 elements (272B): fragment LDS are
// conflict-free (bank = 4*(lane/4) + lane%4).
#define SM_W1   0         // 32x128 f32          = 16384
#define SM_F    16384     // 32x129 f32 (F^T)    = 16512
#define SM_B1   32896     // 128 f32             = 512
#define SM_B2   33408     // 128 f32             = 512
#define SM_RC   33920     // 128 f32             = 512
#define SM_II   34432     // 128 i32             = 512
#define SM_JJ   34944     // 128 i32             = 512
#define SM_HHI  35456     // 128x136 bf16        = 34816
#define SM_HLO  70272     // 34816
#define SM_WHI  105088    // [n][k] 128x136 bf16 = 34816
#define SM_WLO  139904    // 34816
#define EDGE_SMEM_BYTES 174720

// ---------------- utility kernels ----------------
__global__ void zero_kernel(float4* __restrict__ p, int n4) {
    int i = blockIdx.x * blockDim.x + threadIdx.x;
    if (i < n4) p[i] = make_float4(0.f, 0.f, 0.f, 0.f);
}

__global__ void edge_geom(const float* __restrict__ pos,
                          const int* __restrict__ idx_i,
                          const int* __restrict__ idx_j,
                          float* __restrict__ d, float* __restrict__ rc, int E) {
    int e = blockIdx.x * blockDim.x + threadIdx.x;
    if (e >= E) return;
    int a = idx_i[e], b = idx_j[e];
    float dx = pos[a * 3 + 0] - pos[b * 3 + 0];
    float dy = pos[a * 3 + 1] - pos[b * 3 + 1];
    float dz = pos[a * 3 + 2] - pos[b * 3 + 2];
    float dd = sqrtf(dx * dx + dy * dy + dz * dz);
    d[e] = dd;
    rc[e] = (dd < CUTOFF_F) ? 0.5f * (cosf(dd * (PI_F / CUTOFF_F)) + 1.0f) : 0.0f;
}

__global__ void edge_rbf(const int* __restrict__ edge_attr,
                         const float* __restrict__ edge_emb,
                         const float* __restrict__ d,
                         float* __restrict__ F, int E) {
    int t = blockIdx.x * blockDim.x + threadIdx.x;
    if (t >= E * NRBF) return;
    int e = t >> 5, k = t & 31;
    const float width = CUTOFF_F / 31.0f;
    const float coeff = -0.5f / (width * width);
    float u = d[e] - (float)k * width;
    F[t] = expf(coeff * u * u) + edge_emb[edge_attr[e] * NRBF + k];
}

__global__ void embed_zero(const int* __restrict__ z, const int* __restrict__ z_res,
                           const float* __restrict__ ele_emb, const float* __restrict__ res_emb,
                           float* __restrict__ x, float* __restrict__ agg,
                           float* __restrict__ outbuf, int N, int out_n) {
    int t = blockIdx.x * blockDim.x + threadIdx.x;
    if (t < out_n) outbuf[t] = 0.f;
    if (t >= N * NB) return;
    int n = t >> 7, c = t & 127;
    agg[t] = 0.f;
    x[t] = ele_emb[z[n] * NB + c] + res_emb[z_res[n] * NB + c];
}

// ---------------- node GEMM: out = [res +] post( pre(in) @ W + bias ) ----------------
template <int PRE, int POST, int RES>
__global__ __launch_bounds__(256) void node_gemm(
    const float* __restrict__ in, const float* __restrict__ W,
    const float* __restrict__ bias, const float* __restrict__ res,
    float* __restrict__ out, int M)
{
    extern __shared__ float sm[];
    float* sIn = sm;
    float* sW  = sm + 64 * 128;
    const int t = threadIdx.x;
    const int tx = t & 15, ty = t >> 4;
    const int m0 = blockIdx.x * 64;

#pragma unroll
    for (int i = 0; i < 16; i++) {
        int idx = (i * 256 + t) * 4;
        *(float4*)&sW[idx] = *(const float4*)&W[idx];
    }
#pragma unroll
    for (int i = 0; i < 8; i++) {
        int idx = (i * 256 + t) * 4;
        int row = idx >> 7;
        float4 v = make_float4(0.f, 0.f, 0.f, 0.f);
        if (m0 + row < M) v = *(const float4*)&in[(size_t)(m0 + row) * NB + (idx & 127)];
        if (PRE == 1) { v.x = siluf(v.x); v.y = siluf(v.y); v.z = siluf(v.z); v.w = siluf(v.w); }
        *(float4*)&sIn[idx] = v;
    }
    __syncthreads();

    float acc[4][8];
#pragma unroll
    for (int i = 0; i < 4; i++) {
#pragma unroll
        for (int j = 0; j < 8; j++) acc[i][j] = 0.f;
    }

#pragma unroll 2
    for (int k = 0; k < 128; k += 4) {
        float a[4][4];
#pragma unroll
        for (int i = 0; i < 4; i++) {
            float4 v = *(const float4*)&sIn[(ty * 4 + i) * 128 + k];
            a[i][0] = v.x; a[i][1] = v.y; a[i][2] = v.z; a[i][3] = v.w;
        }
#pragma unroll
        for (int kk = 0; kk < 4; kk++) {
            float4 b0 = *(const float4*)&sW[(k + kk) * 128 + tx * 8];
            float4 b1 = *(const float4*)&sW[(k + kk) * 128 + tx * 8 + 4];
            float b[8] = { b0.x, b0.y, b0.z, b0.w, b1.x, b1.y, b1.z, b1.w };
#pragma unroll
            for (int i = 0; i < 4; i++) {
#pragma unroll
                for (int j = 0; j < 8; j++)
                    acc[i][j] = fmaf(a[i][kk], b[j], acc[i][j]);
            }
        }
    }

    float bb[8];
#pragma unroll
    for (int j = 0; j < 8; j++) bb[j] = bias ? bias[tx * 8 + j] : 0.f;

#pragma unroll
    for (int i = 0; i < 4; i++) {
        int m = m0 + ty * 4 + i;
        if (m < M) {
#pragma unroll
            for (int j = 0; j < 8; j++) {
                float v = acc[i][j] + bb[j];
                if (POST == 1) v = sspf(v);
                if (RES == 1) v += res[(size_t)m * NB + tx * 8 + j];
                out[(size_t)m * NB + tx * 8 + j] = v;
            }
        }
    }
}

// ---------------- fused edge kernel: FFMA phase-1 + HMMA bf16 3-term phase-2 ----------------
// 512 threads = 16 warps, tile = 128 edges.
// Phase-1 warp mapping: sub=wid&3 -> rows sub*32+lane; grp=wid>>2 -> cols grp*32..+32.
// Phase-2 warp mapping: mg=wid&3 -> rows mg*32..+32; ng=wid>>2 -> cols ng*32..+32.
__global__ __launch_bounds__(512, 1) void edge_kernel(
    const int* __restrict__ idx_i, const int* __restrict__ idx_j,
    const float* __restrict__ W1, const float* __restrict__ b1,
    const float* __restrict__ W2, const float* __restrict__ b2,
    const float* __restrict__ Ff, const float* __restrict__ rcut,
    const float* __restrict__ xf, float* __restrict__ agg, int E)
{
    extern __shared__ char smch[];
    float* sW1 = (float*)(smch + SM_W1);
    float* sF  = (float*)(smch + SM_F);
    float* sB1 = (float*)(smch + SM_B1);
    float* sB2 = (float*)(smch + SM_B2);
    float* sRC = (float*)(smch + SM_RC);
    int*   sII = (int*)(smch + SM_II);
    int*   sJJ = (int*)(smch + SM_JJ);

    const int t = threadIdx.x;
    const int wid = t >> 5;
    const int lane = t & 31;
    const int eb = blockIdx.x * 128;

    // ---- stage W1 (f32) + biases + per-edge scalars
#pragma unroll
    for (int i = 0; i < 2; i++) {
        int idx = i * 512 + t;
        ((float4*)sW1)[idx] = ((const float4*)W1)[idx];
    }
    if (t < 128) {
        sB1[t] = b1[t];
        sB2[t] = b2[t];
        int e = eb + t;
        float rcv = 0.f; int iiv = 0, jjv = 0;
        if (e < E) { rcv = rcut[e]; iiv = idx_i[e]; jjv = idx_j[e]; }
        sRC[t] = rcv; sII[t] = iiv; sJJ[t] = jjv;
    }

    // ---- stage F transposed: sF[k*129 + r]
#pragma unroll
    for (int i = 0; i < 8; i++) {
        int idx = i * 512 + t;
        int r0 = idx >> 5, k0 = idx & 31;
        float v = (eb + r0 < E) ? Ff[(size_t)(eb + r0) * NRBF + k0] : 0.f;
        sF[k0 * 129 + r0] = v;
    }

    // ---- stage W2 -> bf16 hi/lo, transposed [n][k], stride 136
#pragma unroll
    for (int i = 0; i < 32; i++) {
        int idx = i * 512 + t;
        int k0 = idx >> 7, n0 = idx & 127;
        float w = W2[idx];
        __nv_bfloat16 hi = __float2bfloat16(w);
        __nv_bfloat16 lo = __float2bfloat16(w - __bfloat162float(hi));
        size_t off = ((size_t)n0 * 136 + k0) * 2;
        *(__nv_bfloat16*)(smch + SM_WHI + off) = hi;
        *(__nv_bfloat16*)(smch + SM_WLO + off) = lo;
    }
    __syncthreads();

    // ---- phase 1: H = ssp(F @ W1 + b1), bf16 hi/lo split -> smem
    {
        const int sub = wid & 3;
        const int grp = wid >> 2;
        const int r = sub * 32 + lane;
        const int cb = grp * 32;
#pragma unroll
        for (int half = 0; half < 2; half++) {
            float acc[16];
#pragma unroll
            for (int j = 0; j < 16; j++) acc[j] = 0.f;
            const int c0 = cb + half * 16;
#pragma unroll 4
            for (int k = 0; k < 32; k++) {
                float a = sF[k * 129 + r];
                float4 v0 = *(const float4*)&sW1[k * 128 + c0 + 0];
                float4 v1 = *(const float4*)&sW1[k * 128 + c0 + 4];
                float4 v2 = *(const float4*)&sW1[k * 128 + c0 + 8];
                float4 v3 = *(const float4*)&sW1[k * 128 + c0 + 12];
                acc[0]  = fmaf(a, v0.x, acc[0]);
                acc[1]  = fmaf(a, v0.y, acc[1]);
                acc[2]  = fmaf(a, v0.z, acc[2]);
                acc[3]  = fmaf(a, v0.w, acc[3]);
                acc[4]  = fmaf(a, v1.x, acc[4]);
                acc[5]  = fmaf(a, v1.y, acc[5]);
                acc[6]  = fmaf(a, v1.z, acc[6]);
                acc[7]  = fmaf(a, v1.w, acc[7]);
                acc[8]  = fmaf(a, v2.x, acc[8]);
                acc[9]  = fmaf(a, v2.y, acc[9]);
                acc[10] = fmaf(a, v2.z, acc[10]);
                acc[11] = fmaf(a, v2.w, acc[11]);
                acc[12] = fmaf(a, v3.x, acc[12]);
                acc[13] = fmaf(a, v3.y, acc[13]);
                acc[14] = fmaf(a, v3.z, acc[14]);
                acc[15] = fmaf(a, v3.w, acc[15]);
            }
#pragma unroll
            for (int j = 0; j < 8; j++) {
                int c = c0 + 2 * j;
                float h0 = sspf(acc[2 * j] + sB1[c]);
                float h1 = sspf(acc[2 * j + 1] + sB1[c + 1]);
                __nv_bfloat162 hh = __floats2bfloat162_rn(h0, h1);
                float l0 = h0 - __bfloat162float(hh.x);
                float l1 = h1 - __bfloat162float(hh.y);
                __nv_bfloat162 ll = __floats2bfloat162_rn(l0, l1);
                size_t off = ((size_t)r * 136 + c) * 2;
                *(__nv_bfloat162*)(smch + SM_HHI + off) = hh;
                *(__nv_bfloat162*)(smch + SM_HLO + off) = ll;
            }
        }
    }
    __syncthreads();

    // ---- phase 2: Wij = H @ W2 via HMMA bf16, 3-term split
    const int mg = wid & 3;
    const int ng = wid >> 2;
    const int q = lane & 3;
    const int lr = lane >> 2;

    float acc[2][4][4];
#pragma unroll
    for (int mt = 0; mt < 2; mt++)
#pragma unroll
        for (int nt = 0; nt < 4; nt++)
#pragma unroll
            for (int v = 0; v < 4; v++) acc[mt][nt][v] = 0.f;

#pragma unroll 2
    for (int ks = 0; ks < 8; ks++) {
        const int k0 = ks * 16;
        uint32_t ahi[2][4], alo[2][4], bhi[4][2], blo[4][2];
#pragma unroll
        for (int mt = 0; mt < 2; mt++) {
            int m = mg * 32 + mt * 16 + lr;
            size_t o0 = ((size_t)m * 136 + k0 + 2 * q) * 2;
            size_t o1 = ((size_t)(m + 8) * 136 + k0 + 2 * q) * 2;
            ahi[mt][0] = *(const uint32_t*)(smch + SM_HHI + o0);
            ahi[mt][1] = *(const uint32_t*)(smch + SM_HHI + o1);
            ahi[mt][2] = *(const uint32_t*)(smch + SM_HHI + o0 + 16);
            ahi[mt][3] = *(const uint32_t*)(smch + SM_HHI + o1 + 16);
            alo[mt][0] = *(const uint32_t*)(smch + SM_HLO + o0);
            alo[mt][1] = *(const uint32_t*)(smch + SM_HLO + o1);
            alo[mt][2] = *(const uint32_t*)(smch + SM_HLO + o0 + 16);
            alo[mt][3] = *(const uint32_t*)(smch + SM_HLO + o1 + 16);
        }
#pragma unroll
        for (int nt = 0; nt < 4; nt++) {
            int n = ng * 32 + nt * 8 + lr;
            size_t ob = ((size_t)n * 136 + k0 + 2 * q) * 2;
            bhi[nt][0] = *(const uint32_t*)(smch + SM_WHI + ob);
            bhi[nt][1] = *(const uint32_t*)(smch + SM_WHI + ob + 16);
            blo[nt][0] = *(const uint32_t*)(smch + SM_WLO + ob);
            blo[nt][1] = *(const uint32_t*)(smch + SM_WLO + ob + 16);
        }
#pragma unroll
        for (int mt = 0; mt < 2; mt++) {
#pragma unroll
            for (int nt = 0; nt < 4; nt++) {
                mma_bf16(acc[mt][nt], ahi[mt], bhi[nt]);
                mma_bf16(acc[mt][nt], ahi[mt], blo[nt]);
                mma_bf16(acc[mt][nt], alo[mt], bhi[nt]);
            }
        }
    }

    // ---- epilogue: (Wij + b2) * rc * xf[jj] -> red.v2 into agg[ii]
#pragma unroll
    for (int mt = 0; mt < 2; mt++) {
#pragma unroll
        for (int half = 0; half < 2; half++) {
            int r = mg * 32 + mt * 16 + lr + 8 * half;
            float rc = sRC[r];
            int ii = sII[r], jj = sJJ[r];
            const float* xrow = xf + (size_t)jj * NB;
            float* arow = agg + (size_t)ii * NB;
#pragma unroll
            for (int nt = 0; nt < 4; nt++) {
                int c = ng * 32 + nt * 8 + 2 * q;
                float2 xv = *(const float2*)(xrow + c);
                float2 bv = *(const float2*)&sB2[c];
                float v0 = (acc[mt][nt][2 * half]     + bv.x) * rc * xv.x;
                float v1 = (acc[mt][nt][2 * half + 1] + bv.y) * rc * xv.y;
                red_add_v2(arow + c, v0, v1);
            }
        }
    }
}

// ---------------- head ----------------
__global__ void norm_kernel(const float* __restrict__ x, float* __restrict__ o, int M) {
    int w = (blockIdx.x * blockDim.x + threadIdx.x) >> 5;
    int lane = threadIdx.x & 31;
    if (w >= M) return;
    float4 v = ((const float4*)(x + (size_t)w * NB))[lane];
    float s = v.x * v.x + v.y * v.y + v.z * v.z + v.w * v.w;
#pragma unroll
    for (int o2 = 16; o2 > 0; o2 >>= 1) s += __shfl_xor_sync(0xffffffffu, s, o2);
    float scale = 1.0f / fmaxf(sqrtf(s), 1e-12f);
    ((float4*)(o + (size_t)w * NB))[lane] =
        make_float4(v.x * scale, v.y * scale, v.z * scale, v.w * scale);
}

__global__ void head_final(const float* __restrict__ h, const float* __restrict__ w2,
                           const int* __restrict__ batch, float* __restrict__ out, int M) {
    int w = (blockIdx.x * blockDim.x + threadIdx.x) >> 5;
    int lane = threadIdx.x & 31;
    if (w >= M) return;
    float4 v = ((const float4*)(h + (size_t)w * NB))[lane];
    float4 ww = ((const float4*)w2)[lane];
    float s = siluf(v.x) * ww.x + siluf(v.y) * ww.y + siluf(v.z) * ww.z + siluf(v.w) * ww.w;
#pragma unroll
    for (int o2 = 16; o2 > 0; o2 >>= 1) s += __shfl_xor_sync(0xffffffffu, s, o2);
    if (lane == 0) atomicAdd(&out[batch[w]], s);
}

// ---------------- launch ----------------
typedef void (*ngemm_fn)(const float*, const float*, const float*, const float*, float*, int);

extern "C" void kernel_launch(void* const* d_in, const int* in_sizes, int n_in,
                              void* d_out, int out_size)
{
    const int*   z         = (const int*)d_in[0];
    const int*   z_res     = (const int*)d_in[1];
    const float* pos       = (const float*)d_in[2];
    const int*   idx_i     = (const int*)d_in[3];
    const int*   idx_j     = (const int*)d_in[4];
    const int*   edge_attr = (const int*)d_in[5];
    const int*   batch     = (const int*)d_in[6];
    const float* ele_emb   = (const float*)d_in[7];
    const float* res_emb   = (const float*)d_in[8];
    const float* edge_emb  = (const float*)d_in[9];
    const float* in2f_W    = (const float*)d_in[10];
    const float* filt_W1   = (const float*)d_in[11];
    const float* filt_b1   = (const float*)d_in[12];
    const float* filt_W2   = (const float*)d_in[13];
    const float* filt_b2   = (const float*)d_in[14];
    const float* f2out_W1  = (const float*)d_in[15];
    const float* f2out_b1  = (const float*)d_in[16];
    const float* f2out_W2  = (const float*)d_in[17];
    const float* f2out_b2  = (const float*)d_in[18];
    const float* head_W1   = (const float*)d_in[19];
    const float* head_b1   = (const float*)d_in[20];
    const float* head_W2   = (const float*)d_in[21];
    float* out = (float*)d_out;

    const int N = in_sizes[0];
    const int E = in_sizes[3];

    float *pD, *pRc, *pF, *pX, *pXf, *pAgg, *pT;
    cudaGetSymbolAddress((void**)&pD, g_d);
    cudaGetSymbolAddress((void**)&pRc, g_rc);
    cudaGetSymbolAddress((void**)&pF, g_F);
    cudaGetSymbolAddress((void**)&pX, g_x);
    cudaGetSymbolAddress((void**)&pXf, g_xf);
    cudaGetSymbolAddress((void**)&pAgg, g_agg);
    cudaGetSymbolAddress((void**)&pT, g_t);

    ngemm_fn f_plain = node_gemm<0, 0, 0>;
    ngemm_fn f_ssp   = node_gemm<0, 1, 0>;
    ngemm_fn f_res   = node_gemm<0, 0, 1>;
    ngemm_fn f_silu  = node_gemm<1, 0, 0>;

    const int GEMM_SMEM = (64 * 128 + 128 * 128) * 4;
    cudaFuncSetAttribute((const void*)f_plain, cudaFuncAttributeMaxDynamicSharedMemorySize, GEMM_SMEM);
    cudaFuncSetAttribute((const void*)f_ssp,   cudaFuncAttributeMaxDynamicSharedMemorySize, GEMM_SMEM);
    cudaFuncSetAttribute((const void*)f_res,   cudaFuncAttributeMaxDynamicSharedMemorySize, GEMM_SMEM);
    cudaFuncSetAttribute((const void*)f_silu,  cudaFuncAttributeMaxDynamicSharedMemorySize, GEMM_SMEM);
    cudaFuncSetAttribute((const void*)edge_kernel, cudaFuncAttributeMaxDynamicSharedMemorySize, EDGE_SMEM_BYTES);

    edge_geom<<<(E + 255) / 256, 256>>>(pos, idx_i, idx_j, pD, pRc, E);
    edge_rbf<<<(E * NRBF + 255) / 256, 256>>>(edge_attr, edge_emb, pD, pF, E);
    embed_zero<<<(N * NB + 255) / 256, 256>>>(z, z_res, ele_emb, res_emb, pX, pAgg, out, N, out_size);

    const int gblocks = (N + 63) / 64;
    const int eblocks = (E + 127) / 128;
    const int nz4 = N * NB / 4;

    for (int it = 0; it < 6; it++) {
        if (it > 0)
            zero_kernel<<<(nz4 + 255) / 256, 256>>>((float4*)pAgg, nz4);
        f_plain<<<gblocks, 256, GEMM_SMEM>>>(
            pX, in2f_W + (size_t)it * NB * NB, nullptr, nullptr, pXf, N);
        edge_kernel<<<eblocks, 512, EDGE_SMEM_BYTES>>>(
            idx_i, idx_j,
            filt_W1 + (size_t)it * NRBF * NB, filt_b1 + (size_t)it * NB,
            filt_W2 + (size_t)it * NB * NB,  filt_b2 + (size_t)it * NB,
            pF, pRc, pXf, pAgg, E);
        f_ssp<<<gblocks, 256, GEMM_SMEM>>>(
            pAgg, f2out_W1 + (size_t)it * NB * NB, f2out_b1 + (size_t)it * NB, nullptr, pT, N);
        f_res<<<gblocks, 256, GEMM_SMEM>>>(
            pT, f2out_W2 + (size_t)it * NB * NB, f2out_b2 + (size_t)it * NB, pX, pX, N);
    }

    norm_kernel<<<(N + 7) / 8, 256>>>(pX, pT, N);
    f_silu<<<gblocks, 256, GEMM_SMEM>>>(pT, head_W1, head_b1, nullptr, pXf, N);
    head_final<<<(N + 7) / 8, 256>>>(pXf, head_W2, batch, out, N);
}

// round 6
// speedup vs baseline: 2.3310x; 1.5283x over previous
#include <cuda_runtime.h>
#include <cuda_bf16.h>
#include <stdint.h>
#include <math.h>

#define NATOMS 100000
#define NEDGES 1600000
#define NB 128
#define NRBF 32
#define CUTOFF_F 10.0f
#define PI_F 3.14159265358979f
#define LOG2_F 0.69314718055994531f

// ---------------- scratch (static __device__, no allocations) ----------------
__device__ float g_d[NEDGES];
__device__ float g_rc[NEDGES];
__device__ float g_F[(size_t)NEDGES * NRBF];
__device__ float g_x[(size_t)NATOMS * NB];
__device__ float g_xf[(size_t)NATOMS * NB];
__device__ float g_agg[(size_t)NATOMS * NB];
__device__ float g_t[(size_t)NATOMS * NB];

// ---------------- math helpers ----------------
__device__ __forceinline__ float sspf(float v) {
    // softplus(v) - log(2), fast: max(v,0) + log(1 + exp(-|v|)) - log2
    float ex = __expf(-fabsf(v));
    return fmaxf(v, 0.0f) + __logf(1.0f + ex) - LOG2_F;
}

__device__ __forceinline__ float siluf(float v) {
    return v * (1.0f / (1.0f + __expf(-v)));
}

__device__ __forceinline__ void red_add_v2(float* p, float a, float b) {
    asm volatile("red.global.add.v2.f32 [%0], {%1,%2};"
                 :: "l"(p), "f"(a), "f"(b) : "memory");
}

// HMMA bf16: D(f32) += A(16x16 bf16) * B(16x8 bf16)   [layout validated R5]
__device__ __forceinline__ void mma_bf16(float* c, const uint32_t* a, const uint32_t* b) {
    asm volatile(
        "mma.sync.aligned.m16n8k16.row.col.f32.bf16.bf16.f32 "
        "{%0,%1,%2,%3}, {%4,%5,%6,%7}, {%8,%9}, {%0,%1,%2,%3};"
        : "+f"(c[0]), "+f"(c[1]), "+f"(c[2]), "+f"(c[3])
        : "r"(a[0]), "r"(a[1]), "r"(a[2]), "r"(a[3]), "r"(b[0]), "r"(b[1]));
}

// ---------------- smem byte offsets for edge kernel ----------------
// F/W1 buffers: 32-k rows, stride 40 elems (80B) -> conflict-free fragments.
// H/W2 buffers: 128-k rows, stride 136 elems (272B) -> conflict-free fragments.
#define SM_B1    0          // 128 f32
#define SM_B2    512
#define SM_RC    1024
#define SM_II    1536
#define SM_JJ    2048
#define SM_FHI   2560       // 128 x 40 bf16 = 10240
#define SM_FLO   12800
#define SM_W1HI  23040      // [n][k] 128 x 40 bf16
#define SM_W1LO  33280
#define SM_HHI   43520      // 128 x 136 bf16 = 34816
#define SM_HLO   78336
#define SM_WHI   113152     // [n][k] 128 x 136 bf16
#define SM_WLO   147968
#define EDGE_SMEM_BYTES 182784

// ---------------- utility kernels ----------------
__global__ void zero_kernel(float4* __restrict__ p, int n4) {
    int i = blockIdx.x * blockDim.x + threadIdx.x;
    if (i < n4) p[i] = make_float4(0.f, 0.f, 0.f, 0.f);
}

__global__ void edge_geom(const float* __restrict__ pos,
                          const int* __restrict__ idx_i,
                          const int* __restrict__ idx_j,
                          float* __restrict__ d, float* __restrict__ rc, int E) {
    int e = blockIdx.x * blockDim.x + threadIdx.x;
    if (e >= E) return;
    int a = idx_i[e], b = idx_j[e];
    float dx = pos[a * 3 + 0] - pos[b * 3 + 0];
    float dy = pos[a * 3 + 1] - pos[b * 3 + 1];
    float dz = pos[a * 3 + 2] - pos[b * 3 + 2];
    float dd = sqrtf(dx * dx + dy * dy + dz * dz);
    d[e] = dd;
    rc[e] = (dd < CUTOFF_F) ? 0.5f * (cosf(dd * (PI_F / CUTOFF_F)) + 1.0f) : 0.0f;
}

__global__ void edge_rbf(const int* __restrict__ edge_attr,
                         const float* __restrict__ edge_emb,
                         const float* __restrict__ d,
                         float* __restrict__ F, int E) {
    int t = blockIdx.x * blockDim.x + threadIdx.x;
    if (t >= E * NRBF) return;
    int e = t >> 5, k = t & 31;
    const float width = CUTOFF_F / 31.0f;
    const float coeff = -0.5f / (width * width);
    float u = d[e] - (float)k * width;
    F[t] = expf(coeff * u * u) + edge_emb[edge_attr[e] * NRBF + k];
}

__global__ void embed_zero(const int* __restrict__ z, const int* __restrict__ z_res,
                           const float* __restrict__ ele_emb, const float* __restrict__ res_emb,
                           float* __restrict__ x, float* __restrict__ agg,
                           float* __restrict__ outbuf, int N, int out_n) {
    int t = blockIdx.x * blockDim.x + threadIdx.x;
    if (t < out_n) outbuf[t] = 0.f;
    if (t >= N * NB) return;
    int n = t >> 7, c = t & 127;
    agg[t] = 0.f;
    x[t] = ele_emb[z[n] * NB + c] + res_emb[z_res[n] * NB + c];
}

// ---------------- node GEMM: out = [res +] post( pre(in) @ W + bias ) ----------------
template <int PRE, int POST, int RES>
__global__ __launch_bounds__(256) void node_gemm(
    const float* __restrict__ in, const float* __restrict__ W,
    const float* __restrict__ bias, const float* __restrict__ res,
    float* __restrict__ out, int M)
{
    extern __shared__ float sm[];
    float* sIn = sm;
    float* sW  = sm + 64 * 128;
    const int t = threadIdx.x;
    const int tx = t & 15, ty = t >> 4;
    const int m0 = blockIdx.x * 64;

#pragma unroll
    for (int i = 0; i < 16; i++) {
        int idx = (i * 256 + t) * 4;
        *(float4*)&sW[idx] = *(const float4*)&W[idx];
    }
#pragma unroll
    for (int i = 0; i < 8; i++) {
        int idx = (i * 256 + t) * 4;
        int row = idx >> 7;
        float4 v = make_float4(0.f, 0.f, 0.f, 0.f);
        if (m0 + row < M) v = *(const float4*)&in[(size_t)(m0 + row) * NB + (idx & 127)];
        if (PRE == 1) { v.x = siluf(v.x); v.y = siluf(v.y); v.z = siluf(v.z); v.w = siluf(v.w); }
        *(float4*)&sIn[idx] = v;
    }
    __syncthreads();

    float acc[4][8];
#pragma unroll
    for (int i = 0; i < 4; i++) {
#pragma unroll
        for (int j = 0; j < 8; j++) acc[i][j] = 0.f;
    }

#pragma unroll 2
    for (int k = 0; k < 128; k += 4) {
        float a[4][4];
#pragma unroll
        for (int i = 0; i < 4; i++) {
            float4 v = *(const float4*)&sIn[(ty * 4 + i) * 128 + k];
            a[i][0] = v.x; a[i][1] = v.y; a[i][2] = v.z; a[i][3] = v.w;
        }
#pragma unroll
        for (int kk = 0; kk < 4; kk++) {
            float4 b0 = *(const float4*)&sW[(k + kk) * 128 + tx * 8];
            float4 b1 = *(const float4*)&sW[(k + kk) * 128 + tx * 8 + 4];
            float b[8] = { b0.x, b0.y, b0.z, b0.w, b1.x, b1.y, b1.z, b1.w };
#pragma unroll
            for (int i = 0; i < 4; i++) {
#pragma unroll
                for (int j = 0; j < 8; j++)
                    acc[i][j] = fmaf(a[i][kk], b[j], acc[i][j]);
            }
        }
    }

    float bb[8];
#pragma unroll
    for (int j = 0; j < 8; j++) bb[j] = bias ? bias[tx * 8 + j] : 0.f;

#pragma unroll
    for (int i = 0; i < 4; i++) {
        int m = m0 + ty * 4 + i;
        if (m < M) {
#pragma unroll
            for (int j = 0; j < 8; j++) {
                float v = acc[i][j] + bb[j];
                if (POST == 1) v = sspf(v);
                if (RES == 1) v += res[(size_t)m * NB + tx * 8 + j];
                out[(size_t)m * NB + tx * 8 + j] = v;
            }
        }
    }
}

// ---------------- persistent fused edge kernel: all-HMMA bf16 3-term ----------------
// 512 threads = 16 warps; each block loops over edge tiles of 128.
// Phase-1: H = ssp(F@W1+b1)  (M=128,N=128,K=32 on HMMA)
// Phase-2: Wij = H@W2        (M=128,N=128,K=128 on HMMA)
__global__ __launch_bounds__(512, 1) void edge_kernel(
    const int* __restrict__ idx_i, const int* __restrict__ idx_j,
    const float* __restrict__ W1, const float* __restrict__ b1,
    const float* __restrict__ W2, const float* __restrict__ b2,
    const float* __restrict__ Ff, const float* __restrict__ rcut,
    const float* __restrict__ xf, float* __restrict__ agg, int E, int ntiles)
{
    extern __shared__ char smch[];
    float* sB1 = (float*)(smch + SM_B1);
    float* sB2 = (float*)(smch + SM_B2);
    float* sRC = (float*)(smch + SM_RC);
    int*   sII = (int*)(smch + SM_II);
    int*   sJJ = (int*)(smch + SM_JJ);

    const int t = threadIdx.x;
    const int wid = t >> 5;
    const int lane = t & 31;
    const int q = lane & 3;
    const int lr = lane >> 2;

    // ---- one-time staging: biases, W1 (bf16 hi/lo, [n][k] stride 40), W2 ([n][k] stride 136)
    if (t < 128) { sB1[t] = b1[t]; sB2[t] = b2[t]; }
#pragma unroll
    for (int i = 0; i < 2; i++) {
        int idx4 = i * 512 + t;
        int k = idx4 >> 5;
        int n0 = (idx4 & 31) * 4;
        float4 w = ((const float4*)W1)[idx4];
        float vs[4] = { w.x, w.y, w.z, w.w };
#pragma unroll
        for (int d = 0; d < 4; d++) {
            __nv_bfloat16 hi = __float2bfloat16(vs[d]);
            __nv_bfloat16 lo = __float2bfloat16(vs[d] - __bfloat162float(hi));
            size_t off = ((size_t)(n0 + d) * 40 + k) * 2;
            *(__nv_bfloat16*)(smch + SM_W1HI + off) = hi;
            *(__nv_bfloat16*)(smch + SM_W1LO + off) = lo;
        }
    }
#pragma unroll
    for (int i = 0; i < 8; i++) {
        int idx4 = i * 512 + t;
        int k = idx4 >> 5;
        int n0 = (idx4 & 31) * 4;
        float4 w = ((const float4*)W2)[idx4];
        float vs[4] = { w.x, w.y, w.z, w.w };
#pragma unroll
        for (int d = 0; d < 4; d++) {
            __nv_bfloat16 hi = __float2bfloat16(vs[d]);
            __nv_bfloat16 lo = __float2bfloat16(vs[d] - __bfloat162float(hi));
            size_t off = ((size_t)(n0 + d) * 136 + k) * 2;
            *(__nv_bfloat16*)(smch + SM_WHI + off) = hi;
            *(__nv_bfloat16*)(smch + SM_WLO + off) = lo;
        }
    }

    for (int tile = blockIdx.x; tile < ntiles; tile += gridDim.x) {
        const int eb = tile * 128;

        // ---- stage F (bf16 hi/lo, stride 40) + per-edge scalars
        {
            int r = t >> 2, kq = (t & 3) * 8;
            float4 f0 = make_float4(0.f, 0.f, 0.f, 0.f);
            float4 f1 = make_float4(0.f, 0.f, 0.f, 0.f);
            if (eb + r < E) {
                const float4* src = (const float4*)(Ff + (size_t)(eb + r) * NRBF + kq);
                f0 = src[0]; f1 = src[1];
            }
            __nv_bfloat162 h0 = __floats2bfloat162_rn(f0.x, f0.y);
            __nv_bfloat162 h1 = __floats2bfloat162_rn(f0.z, f0.w);
            __nv_bfloat162 h2 = __floats2bfloat162_rn(f1.x, f1.y);
            __nv_bfloat162 h3 = __floats2bfloat162_rn(f1.z, f1.w);
            __nv_bfloat162 l0 = __floats2bfloat162_rn(f0.x - __bfloat162float(h0.x), f0.y - __bfloat162float(h0.y));
            __nv_bfloat162 l1 = __floats2bfloat162_rn(f0.z - __bfloat162float(h1.x), f0.w - __bfloat162float(h1.y));
            __nv_bfloat162 l2 = __floats2bfloat162_rn(f1.x - __bfloat162float(h2.x), f1.y - __bfloat162float(h2.y));
            __nv_bfloat162 l3 = __floats2bfloat162_rn(f1.z - __bfloat162float(h3.x), f1.w - __bfloat162float(h3.y));
            size_t off = ((size_t)r * 40 + kq) * 2;
            uint4 uh = make_uint4(*(uint32_t*)&h0, *(uint32_t*)&h1, *(uint32_t*)&h2, *(uint32_t*)&h3);
            uint4 ul = make_uint4(*(uint32_t*)&l0, *(uint32_t*)&l1, *(uint32_t*)&l2, *(uint32_t*)&l3);
            *(uint4*)(smch + SM_FHI + off) = uh;
            *(uint4*)(smch + SM_FLO + off) = ul;
        }
        if (t < 128) {
            int e = eb + t;
            float rcv = 0.f; int iiv = 0, jjv = 0;
            if (e < E) { rcv = rcut[e]; iiv = idx_i[e]; jjv = idx_j[e]; }
            sRC[t] = rcv; sII[t] = iiv; sJJ[t] = jjv;
        }
        __syncthreads();

        // ---- phase 1 (HMMA): warp pm=wid&7 -> rows pm*16..+16; pn=wid>>3 -> cols pn*64..+64
        {
            const int pm = wid & 7, pn = wid >> 3;
            const int m0 = pm * 16, n0 = pn * 64;
            uint32_t ahi[2][4], alo[2][4];
#pragma unroll
            for (int ks = 0; ks < 2; ks++) {
                size_t o0 = ((size_t)(m0 + lr) * 40 + ks * 16 + 2 * q) * 2;
                size_t o1 = o0 + 640;
                ahi[ks][0] = *(const uint32_t*)(smch + SM_FHI + o0);
                ahi[ks][1] = *(const uint32_t*)(smch + SM_FHI + o1);
                ahi[ks][2] = *(const uint32_t*)(smch + SM_FHI + o0 + 16);
                ahi[ks][3] = *(const uint32_t*)(smch + SM_FHI + o1 + 16);
                alo[ks][0] = *(const uint32_t*)(smch + SM_FLO + o0);
                alo[ks][1] = *(const uint32_t*)(smch + SM_FLO + o1);
                alo[ks][2] = *(const uint32_t*)(smch + SM_FLO + o0 + 16);
                alo[ks][3] = *(const uint32_t*)(smch + SM_FLO + o1 + 16);
            }
#pragma unroll
            for (int nt = 0; nt < 8; nt++) {
                int n = n0 + nt * 8 + lr;
                float c[4] = { 0.f, 0.f, 0.f, 0.f };
#pragma unroll
                for (int ks = 0; ks < 2; ks++) {
                    size_t ob = ((size_t)n * 40 + ks * 16 + 2 * q) * 2;
                    uint32_t bh[2] = { *(const uint32_t*)(smch + SM_W1HI + ob),
                                       *(const uint32_t*)(smch + SM_W1HI + ob + 16) };
                    uint32_t bl[2] = { *(const uint32_t*)(smch + SM_W1LO + ob),
                                       *(const uint32_t*)(smch + SM_W1LO + ob + 16) };
                    mma_bf16(c, ahi[ks], bh);
                    mma_bf16(c, ahi[ks], bl);
                    mma_bf16(c, alo[ks], bh);
                }
                int cc = n0 + nt * 8 + 2 * q;
                float2 bv = *(const float2*)&sB1[cc];
                float h00 = sspf(c[0] + bv.x), h01 = sspf(c[1] + bv.y);
                float h10 = sspf(c[2] + bv.x), h11 = sspf(c[3] + bv.y);
                __nv_bfloat162 p0 = __floats2bfloat162_rn(h00, h01);
                __nv_bfloat162 p1 = __floats2bfloat162_rn(h10, h11);
                __nv_bfloat162 e0 = __floats2bfloat162_rn(h00 - __bfloat162float(p0.x), h01 - __bfloat162float(p0.y));
                __nv_bfloat162 e1 = __floats2bfloat162_rn(h10 - __bfloat162float(p1.x), h11 - __bfloat162float(p1.y));
                size_t oh0 = ((size_t)(m0 + lr) * 136 + cc) * 2;
                size_t oh1 = oh0 + 136 * 8 * 2;
                *(uint32_t*)(smch + SM_HHI + oh0) = *(uint32_t*)&p0;
                *(uint32_t*)(smch + SM_HHI + oh1) = *(uint32_t*)&p1;
                *(uint32_t*)(smch + SM_HLO + oh0) = *(uint32_t*)&e0;
                *(uint32_t*)(smch + SM_HLO + oh1) = *(uint32_t*)&e1;
            }
        }
        __syncthreads();

        // ---- phase 2 (HMMA 3-term): mg=wid&3 rows, ng=wid>>2 cols (32x32 per warp)
        {
            const int mg = wid & 3;
            const int ng = wid >> 2;

            float acc[2][4][4];
#pragma unroll
            for (int mt = 0; mt < 2; mt++)
#pragma unroll
                for (int nt = 0; nt < 4; nt++)
#pragma unroll
                    for (int v = 0; v < 4; v++) acc[mt][nt][v] = 0.f;

#pragma unroll 2
            for (int ks = 0; ks < 8; ks++) {
                const int k0 = ks * 16;
                uint32_t ahi[2][4], alo[2][4], bhi[4][2], blo[4][2];
#pragma unroll
                for (int mt = 0; mt < 2; mt++) {
                    int m = mg * 32 + mt * 16 + lr;
                    size_t o0 = ((size_t)m * 136 + k0 + 2 * q) * 2;
                    size_t o1 = ((size_t)(m + 8) * 136 + k0 + 2 * q) * 2;
                    ahi[mt][0] = *(const uint32_t*)(smch + SM_HHI + o0);
                    ahi[mt][1] = *(const uint32_t*)(smch + SM_HHI + o1);
                    ahi[mt][2] = *(const uint32_t*)(smch + SM_HHI + o0 + 16);
                    ahi[mt][3] = *(const uint32_t*)(smch + SM_HHI + o1 + 16);
                    alo[mt][0] = *(const uint32_t*)(smch + SM_HLO + o0);
                    alo[mt][1] = *(const uint32_t*)(smch + SM_HLO + o1);
                    alo[mt][2] = *(const uint32_t*)(smch + SM_HLO + o0 + 16);
                    alo[mt][3] = *(const uint32_t*)(smch + SM_HLO + o1 + 16);
                }
#pragma unroll
                for (int nt = 0; nt < 4; nt++) {
                    int n = ng * 32 + nt * 8 + lr;
                    size_t ob = ((size_t)n * 136 + k0 + 2 * q) * 2;
                    bhi[nt][0] = *(const uint32_t*)(smch + SM_WHI + ob);
                    bhi[nt][1] = *(const uint32_t*)(smch + SM_WHI + ob + 16);
                    blo[nt][0] = *(const uint32_t*)(smch + SM_WLO + ob);
                    blo[nt][1] = *(const uint32_t*)(smch + SM_WLO + ob + 16);
                }
#pragma unroll
                for (int mt = 0; mt < 2; mt++) {
#pragma unroll
                    for (int nt = 0; nt < 4; nt++) {
                        mma_bf16(acc[mt][nt], ahi[mt], bhi[nt]);
                        mma_bf16(acc[mt][nt], ahi[mt], blo[nt]);
                        mma_bf16(acc[mt][nt], alo[mt], bhi[nt]);
                    }
                }
            }

            // ---- epilogue: (Wij + b2) * rc * xf[jj] -> red.v2 into agg[ii]
#pragma unroll
            for (int mt = 0; mt < 2; mt++) {
#pragma unroll
                for (int half = 0; half < 2; half++) {
                    int r = mg * 32 + mt * 16 + lr + 8 * half;
                    float rc = sRC[r];
                    int ii = sII[r], jj = sJJ[r];
                    const float* xrow = xf + (size_t)jj * NB;
                    float* arow = agg + (size_t)ii * NB;
#pragma unroll
                    for (int nt = 0; nt < 4; nt++) {
                        int c = ng * 32 + nt * 8 + 2 * q;
                        float2 xv = *(const float2*)(xrow + c);
                        float2 bv = *(const float2*)&sB2[c];
                        float v0 = (acc[mt][nt][2 * half]     + bv.x) * rc * xv.x;
                        float v1 = (acc[mt][nt][2 * half + 1] + bv.y) * rc * xv.y;
                        red_add_v2(arow + c, v0, v1);
                    }
                }
            }
        }
        __syncthreads();
    }
}

// ---------------- head ----------------
__global__ void norm_kernel(const float* __restrict__ x, float* __restrict__ o, int M) {
    int w = (blockIdx.x * blockDim.x + threadIdx.x) >> 5;
    int lane = threadIdx.x & 31;
    if (w >= M) return;
    float4 v = ((const float4*)(x + (size_t)w * NB))[lane];
    float s = v.x * v.x + v.y * v.y + v.z * v.z + v.w * v.w;
#pragma unroll
    for (int o2 = 16; o2 > 0; o2 >>= 1) s += __shfl_xor_sync(0xffffffffu, s, o2);
    float scale = 1.0f / fmaxf(sqrtf(s), 1e-12f);
    ((float4*)(o + (size_t)w * NB))[lane] =
        make_float4(v.x * scale, v.y * scale, v.z * scale, v.w * scale);
}

__global__ void head_final(const float* __restrict__ h, const float* __restrict__ w2,
                           const int* __restrict__ batch, float* __restrict__ out, int M) {
    int w = (blockIdx.x * blockDim.x + threadIdx.x) >> 5;
    int lane = threadIdx.x & 31;
    if (w >= M) return;
    float4 v = ((const float4*)(h + (size_t)w * NB))[lane];
    float4 ww = ((const float4*)w2)[lane];
    float s = siluf(v.x) * ww.x + siluf(v.y) * ww.y + siluf(v.z) * ww.z + siluf(v.w) * ww.w;
#pragma unroll
    for (int o2 = 16; o2 > 0; o2 >>= 1) s += __shfl_xor_sync(0xffffffffu, s, o2);
    if (lane == 0) atomicAdd(&out[batch[w]], s);
}

// ---------------- launch ----------------
typedef void (*ngemm_fn)(const float*, const float*, const float*, const float*, float*, int);

extern "C" void kernel_launch(void* const* d_in, const int* in_sizes, int n_in,
                              void* d_out, int out_size)
{
    const int*   z         = (const int*)d_in[0];
    const int*   z_res     = (const int*)d_in[1];
    const float* pos       = (const float*)d_in[2];
    const int*   idx_i     = (const int*)d_in[3];
    const int*   idx_j     = (const int*)d_in[4];
    const int*   edge_attr = (const int*)d_in[5];
    const int*   batch     = (const int*)d_in[6];
    const float* ele_emb   = (const float*)d_in[7];
    const float* res_emb   = (const float*)d_in[8];
    const float* edge_emb  = (const float*)d_in[9];
    const float* in2f_W    = (const float*)d_in[10];
    const float* filt_W1   = (const float*)d_in[11];
    const float* filt_b1   = (const float*)d_in[12];
    const float* filt_W2   = (const float*)d_in[13];
    const float* filt_b2   = (const float*)d_in[14];
    const float* f2out_W1  = (const float*)d_in[15];
    const float* f2out_b1  = (const float*)d_in[16];
    const float* f2out_W2  = (const float*)d_in[17];
    const float* f2out_b2  = (const float*)d_in[18];
    const float* head_W1   = (const float*)d_in[19];
    const float* head_b1   = (const float*)d_in[20];
    const float* head_W2   = (const float*)d_in[21];
    float* out = (float*)d_out;

    const int N = in_sizes[0];
    const int E = in_sizes[3];

    float *pD, *pRc, *pF, *pX, *pXf, *pAgg, *pT;
    cudaGetSymbolAddress((void**)&pD, g_d);
    cudaGetSymbolAddress((void**)&pRc, g_rc);
    cudaGetSymbolAddress((void**)&pF, g_F);
    cudaGetSymbolAddress((void**)&pX, g_x);
    cudaGetSymbolAddress((void**)&pXf, g_xf);
    cudaGetSymbolAddress((void**)&pAgg, g_agg);
    cudaGetSymbolAddress((void**)&pT, g_t);

    ngemm_fn f_plain = node_gemm<0, 0, 0>;
    ngemm_fn f_ssp   = node_gemm<0, 1, 0>;
    ngemm_fn f_res   = node_gemm<0, 0, 1>;
    ngemm_fn f_silu  = node_gemm<1, 0, 0>;

    const int GEMM_SMEM = (64 * 128 + 128 * 128) * 4;
    cudaFuncSetAttribute((const void*)f_plain, cudaFuncAttributeMaxDynamicSharedMemorySize, GEMM_SMEM);
    cudaFuncSetAttribute((const void*)f_ssp,   cudaFuncAttributeMaxDynamicSharedMemorySize, GEMM_SMEM);
    cudaFuncSetAttribute((const void*)f_res,   cudaFuncAttributeMaxDynamicSharedMemorySize, GEMM_SMEM);
    cudaFuncSetAttribute((const void*)f_silu,  cudaFuncAttributeMaxDynamicSharedMemorySize, GEMM_SMEM);
    cudaFuncSetAttribute((const void*)edge_kernel, cudaFuncAttributeMaxDynamicSharedMemorySize, EDGE_SMEM_BYTES);

    int nsm = 148;
    cudaDeviceGetAttribute(&nsm, cudaDevAttrMultiProcessorCount, 0);
    const int ntiles = (E + 127) / 128;

    edge_geom<<<(E + 255) / 256, 256>>>(pos, idx_i, idx_j, pD, pRc, E);
    edge_rbf<<<(E * NRBF + 255) / 256, 256>>>(edge_attr, edge_emb, pD, pF, E);
    embed_zero<<<(N * NB + 255) / 256, 256>>>(z, z_res, ele_emb, res_emb, pX, pAgg, out, N, out_size);

    const int gblocks = (N + 63) / 64;
    const int nz4 = N * NB / 4;

    for (int it = 0; it < 6; it++) {
        if (it > 0)
            zero_kernel<<<(nz4 + 255) / 256, 256>>>((float4*)pAgg, nz4);
        f_plain<<<gblocks, 256, GEMM_SMEM>>>(
            pX, in2f_W + (size_t)it * NB * NB, nullptr, nullptr, pXf, N);
        edge_kernel<<<nsm, 512, EDGE_SMEM_BYTES>>>(
            idx_i, idx_j,
            filt_W1 + (size_t)it * NRBF * NB, filt_b1 + (size_t)it * NB,
            filt_W2 + (size_t)it * NB * NB,  filt_b2 + (size_t)it * NB,
            pF, pRc, pXf, pAgg, E, ntiles);
        f_ssp<<<gblocks, 256, GEMM_SMEM>>>(
            pAgg, f2out_W1 + (size_t)it * NB * NB, f2out_b1 + (size_t)it * NB, nullptr, pT, N);
        f_res<<<gblocks, 256, GEMM_SMEM>>>(
            pT, f2out_W2 + (size_t)it * NB * NB, f2out_b2 + (size_t)it * NB, pX, pX, N);
    }

    norm_kernel<<<(N + 7) / 8, 256>>>(pX, pT, N);
    f_silu<<<gblocks, 256, GEMM_SMEM>>>(pT, head_W1, head_b1, nullptr, pXf, N);
    head_final<<<(N + 7) / 8, 256>>>(pXf, head_W2, batch, out, N);
}

// round 7
// speedup vs baseline: 2.8352x; 1.2163x over previous
#include <cuda_runtime.h>
#include <cuda_bf16.h>
#include <stdint.h>
#include <math.h>

#define NATOMS 100000
#define NEDGES 1600000
#define NB 128
#define NRBF 32
#define CUTOFF_F 10.0f
#define PI_F 3.14159265358979f
#define LOG2_F 0.69314718055994531f

// ---------------- scratch (static __device__, no allocations) ----------------
__device__ float g_d[NEDGES];
__device__ float g_rc[NEDGES];
__device__ float g_F[(size_t)NEDGES * NRBF];
__device__ float g_x[(size_t)NATOMS * NB];
__device__ float g_xf[(size_t)NATOMS * NB];
__device__ float g_agg[(size_t)NATOMS * NB];
__device__ float g_t[(size_t)NATOMS * NB];

// ---------------- math helpers ----------------
__device__ __forceinline__ float sspf(float v) {
    float ex = __expf(-fabsf(v));
    return fmaxf(v, 0.0f) + __logf(1.0f + ex) - LOG2_F;
}

__device__ __forceinline__ float siluf(float v) {
    return v * (1.0f / (1.0f + __expf(-v)));
}

__device__ __forceinline__ void red_add_v2(float* p, float a, float b) {
    asm volatile("red.global.add.v2.f32 [%0], {%1,%2};"
                 :: "l"(p), "f"(a), "f"(b) : "memory");
}

// HMMA bf16: D(f32) += A(16x16 bf16) * B(16x8 bf16)   [layout validated R5/R6]
__device__ __forceinline__ void mma_bf16(float* c, const uint32_t* a, const uint32_t* b) {
    asm volatile(
        "mma.sync.aligned.m16n8k16.row.col.f32.bf16.bf16.f32 "
        "{%0,%1,%2,%3}, {%4,%5,%6,%7}, {%8,%9}, {%0,%1,%2,%3};"
        : "+f"(c[0]), "+f"(c[1]), "+f"(c[2]), "+f"(c[3])
        : "r"(a[0]), "r"(a[1]), "r"(a[2]), "r"(a[3]), "r"(b[0]), "r"(b[1]));
}

// ---------------- smem byte offsets for edge kernel ----------------
#define SM_B1    0
#define SM_B2    512
#define SM_RC    1024
#define SM_II    1536
#define SM_JJ    2048
#define SM_FHI   2560
#define SM_FLO   12800
#define SM_W1HI  23040
#define SM_W1LO  33280
#define SM_HHI   43520
#define SM_HLO   78336
#define SM_WHI   113152
#define SM_WLO   147968
#define EDGE_SMEM_BYTES 182784

// ---------------- smem byte offsets for node kernel ----------------
#define NSM_B    0          // 128 f32 bias
#define NSM_INHI 512        // 128 x 136 bf16 = 34816
#define NSM_INLO 35328
#define NSM_WHI  70144
#define NSM_WLO  104960
#define NODE_SMEM_BYTES 139776

// ---------------- utility kernels ----------------
__global__ void zero_kernel(float4* __restrict__ p, int n4) {
    int i = blockIdx.x * blockDim.x + threadIdx.x;
    if (i < n4) p[i] = make_float4(0.f, 0.f, 0.f, 0.f);
}

__global__ void edge_geom(const float* __restrict__ pos,
                          const int* __restrict__ idx_i,
                          const int* __restrict__ idx_j,
                          float* __restrict__ d, float* __restrict__ rc, int E) {
    int e = blockIdx.x * blockDim.x + threadIdx.x;
    if (e >= E) return;
    int a = idx_i[e], b = idx_j[e];
    float dx = pos[a * 3 + 0] - pos[b * 3 + 0];
    float dy = pos[a * 3 + 1] - pos[b * 3 + 1];
    float dz = pos[a * 3 + 2] - pos[b * 3 + 2];
    float dd = sqrtf(dx * dx + dy * dy + dz * dz);
    d[e] = dd;
    rc[e] = (dd < CUTOFF_F) ? 0.5f * (cosf(dd * (PI_F / CUTOFF_F)) + 1.0f) : 0.0f;
}

__global__ void edge_rbf(const int* __restrict__ edge_attr,
                         const float* __restrict__ edge_emb,
                         const float* __restrict__ d,
                         float* __restrict__ F, int E) {
    int t = blockIdx.x * blockDim.x + threadIdx.x;
    if (t >= E * NRBF) return;
    int e = t >> 5, k = t & 31;
    const float width = CUTOFF_F / 31.0f;
    const float coeff = -0.5f / (width * width);
    float u = d[e] - (float)k * width;
    F[t] = expf(coeff * u * u) + edge_emb[edge_attr[e] * NRBF + k];
}

__global__ void embed_zero(const int* __restrict__ z, const int* __restrict__ z_res,
                           const float* __restrict__ ele_emb, const float* __restrict__ res_emb,
                           float* __restrict__ x, float* __restrict__ agg,
                           float* __restrict__ outbuf, int N, int out_n) {
    int t = blockIdx.x * blockDim.x + threadIdx.x;
    if (t < out_n) outbuf[t] = 0.f;
    if (t >= N * NB) return;
    int n = t >> 7, c = t & 127;
    agg[t] = 0.f;
    x[t] = ele_emb[z[n] * NB + c] + res_emb[z_res[n] * NB + c];
}

// ---------------- persistent HMMA node GEMM: out = [res +] post( pre(in) @ W + bias ) ----------------
// 512 threads = 16 warps; W staged once (bf16 hi/lo, [n][k] stride 136);
// loops 128-row tiles: stage input split -> 3-term HMMA -> epilogue.
template <int PRE, int POST, int RES>
__global__ __launch_bounds__(512, 1) void hmma_node_gemm(
    const float* __restrict__ in, const float* __restrict__ W,
    const float* __restrict__ bias, const float* __restrict__ res,
    float* __restrict__ out, int M, int ntiles)
{
    extern __shared__ char smch[];
    float* sB = (float*)(smch + NSM_B);

    const int t = threadIdx.x;
    const int wid = t >> 5;
    const int lane = t & 31;
    const int q = lane & 3;
    const int lr = lane >> 2;

    // one-time: bias + W (bf16 hi/lo, [n][k] stride 136)
    if (t < 128) sB[t] = bias ? bias[t] : 0.f;
#pragma unroll
    for (int i = 0; i < 8; i++) {
        int idx4 = i * 512 + t;
        int k = idx4 >> 5;
        int n0 = (idx4 & 31) * 4;
        float4 w = ((const float4*)W)[idx4];
        float vs[4] = { w.x, w.y, w.z, w.w };
#pragma unroll
        for (int d = 0; d < 4; d++) {
            __nv_bfloat16 hi = __float2bfloat16(vs[d]);
            __nv_bfloat16 lo = __float2bfloat16(vs[d] - __bfloat162float(hi));
            size_t off = ((size_t)(n0 + d) * 136 + k) * 2;
            *(__nv_bfloat16*)(smch + NSM_WHI + off) = hi;
            *(__nv_bfloat16*)(smch + NSM_WLO + off) = lo;
        }
    }
    __syncthreads();

    const int mg = wid & 3;
    const int ng = wid >> 2;

    for (int tile = blockIdx.x; tile < ntiles; tile += gridDim.x) {
        const int m0 = tile * 128;

        // stage input rows: thread t -> row t>>2, cols (t&3)*32..+32
        {
            int r = t >> 2, cq = (t & 3) * 32;
            const float4* src = (const float4*)(in + (size_t)(m0 + r) * NB + cq);
            bool ok = (m0 + r < M);
#pragma unroll
            for (int j = 0; j < 8; j++) {
                float4 f = ok ? src[j] : make_float4(0.f, 0.f, 0.f, 0.f);
                if (PRE == 1) { f.x = siluf(f.x); f.y = siluf(f.y); f.z = siluf(f.z); f.w = siluf(f.w); }
                __nv_bfloat162 h0 = __floats2bfloat162_rn(f.x, f.y);
                __nv_bfloat162 h1 = __floats2bfloat162_rn(f.z, f.w);
                __nv_bfloat162 l0 = __floats2bfloat162_rn(f.x - __bfloat162float(h0.x), f.y - __bfloat162float(h0.y));
                __nv_bfloat162 l1 = __floats2bfloat162_rn(f.z - __bfloat162float(h1.x), f.w - __bfloat162float(h1.y));
                size_t off = ((size_t)r * 136 + cq + j * 4) * 2;
                *(uint2*)(smch + NSM_INHI + off) = make_uint2(*(uint32_t*)&h0, *(uint32_t*)&h1);
                *(uint2*)(smch + NSM_INLO + off) = make_uint2(*(uint32_t*)&l0, *(uint32_t*)&l1);
            }
        }
        __syncthreads();

        // 3-term HMMA: 32x32 per warp
        float acc[2][4][4];
#pragma unroll
        for (int mt = 0; mt < 2; mt++)
#pragma unroll
            for (int nt = 0; nt < 4; nt++)
#pragma unroll
                for (int v = 0; v < 4; v++) acc[mt][nt][v] = 0.f;

#pragma unroll 2
        for (int ks = 0; ks < 8; ks++) {
            const int k0 = ks * 16;
            uint32_t ahi[2][4], alo[2][4], bhi[4][2], blo[4][2];
#pragma unroll
            for (int mt = 0; mt < 2; mt++) {
                int m = mg * 32 + mt * 16 + lr;
                size_t o0 = ((size_t)m * 136 + k0 + 2 * q) * 2;
                size_t o1 = ((size_t)(m + 8) * 136 + k0 + 2 * q) * 2;
                ahi[mt][0] = *(const uint32_t*)(smch + NSM_INHI + o0);
                ahi[mt][1] = *(const uint32_t*)(smch + NSM_INHI + o1);
                ahi[mt][2] = *(const uint32_t*)(smch + NSM_INHI + o0 + 16);
                ahi[mt][3] = *(const uint32_t*)(smch + NSM_INHI + o1 + 16);
                alo[mt][0] = *(const uint32_t*)(smch + NSM_INLO + o0);
                alo[mt][1] = *(const uint32_t*)(smch + NSM_INLO + o1);
                alo[mt][2] = *(const uint32_t*)(smch + NSM_INLO + o0 + 16);
                alo[mt][3] = *(const uint32_t*)(smch + NSM_INLO + o1 + 16);
            }
#pragma unroll
            for (int nt = 0; nt < 4; nt++) {
                int n = ng * 32 + nt * 8 + lr;
                size_t ob = ((size_t)n * 136 + k0 + 2 * q) * 2;
                bhi[nt][0] = *(const uint32_t*)(smch + NSM_WHI + ob);
                bhi[nt][1] = *(const uint32_t*)(smch + NSM_WHI + ob + 16);
                blo[nt][0] = *(const uint32_t*)(smch + NSM_WLO + ob);
                blo[nt][1] = *(const uint32_t*)(smch + NSM_WLO + ob + 16);
            }
#pragma unroll
            for (int mt = 0; mt < 2; mt++) {
#pragma unroll
                for (int nt = 0; nt < 4; nt++) {
                    mma_bf16(acc[mt][nt], ahi[mt], bhi[nt]);
                    mma_bf16(acc[mt][nt], ahi[mt], blo[nt]);
                    mma_bf16(acc[mt][nt], alo[mt], bhi[nt]);
                }
            }
        }

        // epilogue
#pragma unroll
        for (int mt = 0; mt < 2; mt++) {
#pragma unroll
            for (int half = 0; half < 2; half++) {
                int rr = mg * 32 + mt * 16 + lr + 8 * half;
                int m = m0 + rr;
                if (m < M) {
                    const float* rrow = res + (size_t)m * NB;
                    float* orow = out + (size_t)m * NB;
#pragma unroll
                    for (int nt = 0; nt < 4; nt++) {
                        int c = ng * 32 + nt * 8 + 2 * q;
                        float2 bv = *(const float2*)&sB[c];
                        float v0 = acc[mt][nt][2 * half]     + bv.x;
                        float v1 = acc[mt][nt][2 * half + 1] + bv.y;
                        if (POST == 1) { v0 = sspf(v0); v1 = sspf(v1); }
                        if (RES == 1) {
                            float2 rv = *(const float2*)(rrow + c);
                            v0 += rv.x; v1 += rv.y;
                        }
                        *(float2*)(orow + c) = make_float2(v0, v1);
                    }
                }
            }
        }
        __syncthreads();
    }
}

// ---------------- persistent fused edge kernel: all-HMMA bf16 3-term (unchanged R6) ----------------
__global__ __launch_bounds__(512, 1) void edge_kernel(
    const int* __restrict__ idx_i, const int* __restrict__ idx_j,
    const float* __restrict__ W1, const float* __restrict__ b1,
    const float* __restrict__ W2, const float* __restrict__ b2,
    const float* __restrict__ Ff, const float* __restrict__ rcut,
    const float* __restrict__ xf, float* __restrict__ agg, int E, int ntiles)
{
    extern __shared__ char smch[];
    float* sB1 = (float*)(smch + SM_B1);
    float* sB2 = (float*)(smch + SM_B2);
    float* sRC = (float*)(smch + SM_RC);
    int*   sII = (int*)(smch + SM_II);
    int*   sJJ = (int*)(smch + SM_JJ);

    const int t = threadIdx.x;
    const int wid = t >> 5;
    const int lane = t & 31;
    const int q = lane & 3;
    const int lr = lane >> 2;

    if (t < 128) { sB1[t] = b1[t]; sB2[t] = b2[t]; }
#pragma unroll
    for (int i = 0; i < 2; i++) {
        int idx4 = i * 512 + t;
        int k = idx4 >> 5;
        int n0 = (idx4 & 31) * 4;
        float4 w = ((const float4*)W1)[idx4];
        float vs[4] = { w.x, w.y, w.z, w.w };
#pragma unroll
        for (int d = 0; d < 4; d++) {
            __nv_bfloat16 hi = __float2bfloat16(vs[d]);
            __nv_bfloat16 lo = __float2bfloat16(vs[d] - __bfloat162float(hi));
            size_t off = ((size_t)(n0 + d) * 40 + k) * 2;
            *(__nv_bfloat16*)(smch + SM_W1HI + off) = hi;
            *(__nv_bfloat16*)(smch + SM_W1LO + off) = lo;
        }
    }
#pragma unroll
    for (int i = 0; i < 8; i++) {
        int idx4 = i * 512 + t;
        int k = idx4 >> 5;
        int n0 = (idx4 & 31) * 4;
        float4 w = ((const float4*)W2)[idx4];
        float vs[4] = { w.x, w.y, w.z, w.w };
#pragma unroll
        for (int d = 0; d < 4; d++) {
            __nv_bfloat16 hi = __float2bfloat16(vs[d]);
            __nv_bfloat16 lo = __float2bfloat16(vs[d] - __bfloat162float(hi));
            size_t off = ((size_t)(n0 + d) * 136 + k) * 2;
            *(__nv_bfloat16*)(smch + SM_WHI + off) = hi;
            *(__nv_bfloat16*)(smch + SM_WLO + off) = lo;
        }
    }

    for (int tile = blockIdx.x; tile < ntiles; tile += gridDim.x) {
        const int eb = tile * 128;

        {
            int r = t >> 2, kq = (t & 3) * 8;
            float4 f0 = make_float4(0.f, 0.f, 0.f, 0.f);
            float4 f1 = make_float4(0.f, 0.f, 0.f, 0.f);
            if (eb + r < E) {
                const float4* src = (const float4*)(Ff + (size_t)(eb + r) * NRBF + kq);
                f0 = src[0]; f1 = src[1];
            }
            __nv_bfloat162 h0 = __floats2bfloat162_rn(f0.x, f0.y);
            __nv_bfloat162 h1 = __floats2bfloat162_rn(f0.z, f0.w);
            __nv_bfloat162 h2 = __floats2bfloat162_rn(f1.x, f1.y);
            __nv_bfloat162 h3 = __floats2bfloat162_rn(f1.z, f1.w);
            __nv_bfloat162 l0 = __floats2bfloat162_rn(f0.x - __bfloat162float(h0.x), f0.y - __bfloat162float(h0.y));
            __nv_bfloat162 l1 = __floats2bfloat162_rn(f0.z - __bfloat162float(h1.x), f0.w - __bfloat162float(h1.y));
            __nv_bfloat162 l2 = __floats2bfloat162_rn(f1.x - __bfloat162float(h2.x), f1.y - __bfloat162float(h2.y));
            __nv_bfloat162 l3 = __floats2bfloat162_rn(f1.z - __bfloat162float(h3.x), f1.w - __bfloat162float(h3.y));
            size_t off = ((size_t)r * 40 + kq) * 2;
            uint4 uh = make_uint4(*(uint32_t*)&h0, *(uint32_t*)&h1, *(uint32_t*)&h2, *(uint32_t*)&h3);
            uint4 ul = make_uint4(*(uint32_t*)&l0, *(uint32_t*)&l1, *(uint32_t*)&l2, *(uint32_t*)&l3);
            *(uint4*)(smch + SM_FHI + off) = uh;
            *(uint4*)(smch + SM_FLO + off) = ul;
        }
        if (t < 128) {
            int e = eb + t;
            float rcv = 0.f; int iiv = 0, jjv = 0;
            if (e < E) { rcv = rcut[e]; iiv = idx_i[e]; jjv = idx_j[e]; }
            sRC[t] = rcv; sII[t] = iiv; sJJ[t] = jjv;
        }
        __syncthreads();

        {
            const int pm = wid & 7, pn = wid >> 3;
            const int m0 = pm * 16, n0 = pn * 64;
            uint32_t ahi[2][4], alo[2][4];
#pragma unroll
            for (int ks = 0; ks < 2; ks++) {
                size_t o0 = ((size_t)(m0 + lr) * 40 + ks * 16 + 2 * q) * 2;
                size_t o1 = o0 + 640;
                ahi[ks][0] = *(const uint32_t*)(smch + SM_FHI + o0);
                ahi[ks][1] = *(const uint32_t*)(smch + SM_FHI + o1);
                ahi[ks][2] = *(const uint32_t*)(smch + SM_FHI + o0 + 16);
                ahi[ks][3] = *(const uint32_t*)(smch + SM_FHI + o1 + 16);
                alo[ks][0] = *(const uint32_t*)(smch + SM_FLO + o0);
                alo[ks][1] = *(const uint32_t*)(smch + SM_FLO + o1);
                alo[ks][2] = *(const uint32_t*)(smch + SM_FLO + o0 + 16);
                alo[ks][3] = *(const uint32_t*)(smch + SM_FLO + o1 + 16);
            }
#pragma unroll
            for (int nt = 0; nt < 8; nt++) {
                int n = n0 + nt * 8 + lr;
                float c[4] = { 0.f, 0.f, 0.f, 0.f };
#pragma unroll
                for (int ks = 0; ks < 2; ks++) {
                    size_t ob = ((size_t)n * 40 + ks * 16 + 2 * q) * 2;
                    uint32_t bh[2] = { *(const uint32_t*)(smch + SM_W1HI + ob),
                                       *(const uint32_t*)(smch + SM_W1HI + ob + 16) };
                    uint32_t bl[2] = { *(const uint32_t*)(smch + SM_W1LO + ob),
                                       *(const uint32_t*)(smch + SM_W1LO + ob + 16) };
                    mma_bf16(c, ahi[ks], bh);
                    mma_bf16(c, ahi[ks], bl);
                    mma_bf16(c, alo[ks], bh);
                }
                int cc = n0 + nt * 8 + 2 * q;
                float2 bv = *(const float2*)&sB1[cc];
                float h00 = sspf(c[0] + bv.x), h01 = sspf(c[1] + bv.y);
                float h10 = sspf(c[2] + bv.x), h11 = sspf(c[3] + bv.y);
                __nv_bfloat162 p0 = __floats2bfloat162_rn(h00, h01);
                __nv_bfloat162 p1 = __floats2bfloat162_rn(h10, h11);
                __nv_bfloat162 e0 = __floats2bfloat162_rn(h00 - __bfloat162float(p0.x), h01 - __bfloat162float(p0.y));
                __nv_bfloat162 e1 = __floats2bfloat162_rn(h10 - __bfloat162float(p1.x), h11 - __bfloat162float(p1.y));
                size_t oh0 = ((size_t)(m0 + lr) * 136 + cc) * 2;
                size_t oh1 = oh0 + 136 * 8 * 2;
                *(uint32_t*)(smch + SM_HHI + oh0) = *(uint32_t*)&p0;
                *(uint32_t*)(smch + SM_HHI + oh1) = *(uint32_t*)&p1;
                *(uint32_t*)(smch + SM_HLO + oh0) = *(uint32_t*)&e0;
                *(uint32_t*)(smch + SM_HLO + oh1) = *(uint32_t*)&e1;
            }
        }
        __syncthreads();

        {
            const int mg = wid & 3;
            const int ng = wid >> 2;

            float acc[2][4][4];
#pragma unroll
            for (int mt = 0; mt < 2; mt++)
#pragma unroll
                for (int nt = 0; nt < 4; nt++)
#pragma unroll
                    for (int v = 0; v < 4; v++) acc[mt][nt][v] = 0.f;

#pragma unroll 2
            for (int ks = 0; ks < 8; ks++) {
                const int k0 = ks * 16;
                uint32_t ahi[2][4], alo[2][4], bhi[4][2], blo[4][2];
#pragma unroll
                for (int mt = 0; mt < 2; mt++) {
                    int m = mg * 32 + mt * 16 + lr;
                    size_t o0 = ((size_t)m * 136 + k0 + 2 * q) * 2;
                    size_t o1 = ((size_t)(m + 8) * 136 + k0 + 2 * q) * 2;
                    ahi[mt][0] = *(const uint32_t*)(smch + SM_HHI + o0);
                    ahi[mt][1] = *(const uint32_t*)(smch + SM_HHI + o1);
                    ahi[mt][2] = *(const uint32_t*)(smch + SM_HHI + o0 + 16);
                    ahi[mt][3] = *(const uint32_t*)(smch + SM_HHI + o1 + 16);
                    alo[mt][0] = *(const uint32_t*)(smch + SM_HLO + o0);
                    alo[mt][1] = *(const uint32_t*)(smch + SM_HLO + o1);
                    alo[mt][2] = *(const uint32_t*)(smch + SM_HLO + o0 + 16);
                    alo[mt][3] = *(const uint32_t*)(smch + SM_HLO + o1 + 16);
                }
#pragma unroll
                for (int nt = 0; nt < 4; nt++) {
                    int n = ng * 32 + nt * 8 + lr;
                    size_t ob = ((size_t)n * 136 + k0 + 2 * q) * 2;
                    bhi[nt][0] = *(const uint32_t*)(smch + SM_WHI + ob);
                    bhi[nt][1] = *(const uint32_t*)(smch + SM_WHI + ob + 16);
                    blo[nt][0] = *(const uint32_t*)(smch + SM_WLO + ob);
                    blo[nt][1] = *(const uint32_t*)(smch + SM_WLO + ob + 16);
                }
#pragma unroll
                for (int mt = 0; mt < 2; mt++) {
#pragma unroll
                    for (int nt = 0; nt < 4; nt++) {
                        mma_bf16(acc[mt][nt], ahi[mt], bhi[nt]);
                        mma_bf16(acc[mt][nt], ahi[mt], blo[nt]);
                        mma_bf16(acc[mt][nt], alo[mt], bhi[nt]);
                    }
                }
            }

#pragma unroll
            for (int mt = 0; mt < 2; mt++) {
#pragma unroll
                for (int half = 0; half < 2; half++) {
                    int r = mg * 32 + mt * 16 + lr + 8 * half;
                    float rc = sRC[r];
                    int ii = sII[r], jj = sJJ[r];
                    const float* xrow = xf + (size_t)jj * NB;
                    float* arow = agg + (size_t)ii * NB;
#pragma unroll
                    for (int nt = 0; nt < 4; nt++) {
                        int c = ng * 32 + nt * 8 + 2 * q;
                        float2 xv = *(const float2*)(xrow + c);
                        float2 bv = *(const float2*)&sB2[c];
                        float v0 = (acc[mt][nt][2 * half]     + bv.x) * rc * xv.x;
                        float v1 = (acc[mt][nt][2 * half + 1] + bv.y) * rc * xv.y;
                        red_add_v2(arow + c, v0, v1);
                    }
                }
            }
        }
        __syncthreads();
    }
}

// ---------------- head ----------------
__global__ void norm_kernel(const float* __restrict__ x, float* __restrict__ o, int M) {
    int w = (blockIdx.x * blockDim.x + threadIdx.x) >> 5;
    int lane = threadIdx.x & 31;
    if (w >= M) return;
    float4 v = ((const float4*)(x + (size_t)w * NB))[lane];
    float s = v.x * v.x + v.y * v.y + v.z * v.z + v.w * v.w;
#pragma unroll
    for (int o2 = 16; o2 > 0; o2 >>= 1) s += __shfl_xor_sync(0xffffffffu, s, o2);
    float scale = 1.0f / fmaxf(sqrtf(s), 1e-12f);
    ((float4*)(o + (size_t)w * NB))[lane] =
        make_float4(v.x * scale, v.y * scale, v.z * scale, v.w * scale);
}

__global__ void head_final(const float* __restrict__ h, const float* __restrict__ w2,
                           const int* __restrict__ batch, float* __restrict__ out, int M) {
    int w = (blockIdx.x * blockDim.x + threadIdx.x) >> 5;
    int lane = threadIdx.x & 31;
    if (w >= M) return;
    float4 v = ((const float4*)(h + (size_t)w * NB))[lane];
    float4 ww = ((const float4*)w2)[lane];
    float s = siluf(v.x) * ww.x + siluf(v.y) * ww.y + siluf(v.z) * ww.z + siluf(v.w) * ww.w;
#pragma unroll
    for (int o2 = 16; o2 > 0; o2 >>= 1) s += __shfl_xor_sync(0xffffffffu, s, o2);
    if (lane == 0) atomicAdd(&out[batch[w]], s);
}

// ---------------- launch ----------------
typedef void (*ngemm_fn)(const float*, const float*, const float*, const float*, float*, int, int);

extern "C" void kernel_launch(void* const* d_in, const int* in_sizes, int n_in,
                              void* d_out, int out_size)
{
    const int*   z         = (const int*)d_in[0];
    const int*   z_res     = (const int*)d_in[1];
    const float* pos       = (const float*)d_in[2];
    const int*   idx_i     = (const int*)d_in[3];
    const int*   idx_j     = (const int*)d_in[4];
    const int*   edge_attr = (const int*)d_in[5];
    const int*   batch     = (const int*)d_in[6];
    const float* ele_emb   = (const float*)d_in[7];
    const float* res_emb   = (const float*)d_in[8];
    const float* edge_emb  = (const float*)d_in[9];
    const float* in2f_W    = (const float*)d_in[10];
    const float* filt_W1   = (const float*)d_in[11];
    const float* filt_b1   = (const float*)d_in[12];
    const float* filt_W2   = (const float*)d_in[13];
    const float* filt_b2   = (const float*)d_in[14];
    const float* f2out_W1  = (const float*)d_in[15];
    const float* f2out_b1  = (const float*)d_in[16];
    const float* f2out_W2  = (const float*)d_in[17];
    const float* f2out_b2  = (const float*)d_in[18];
    const float* head_W1   = (const float*)d_in[19];
    const float* head_b1   = (const float*)d_in[20];
    const float* head_W2   = (const float*)d_in[21];
    float* out = (float*)d_out;

    const int N = in_sizes[0];
    const int E = in_sizes[3];

    float *pD, *pRc, *pF, *pX, *pXf, *pAgg, *pT;
    cudaGetSymbolAddress((void**)&pD, g_d);
    cudaGetSymbolAddress((void**)&pRc, g_rc);
    cudaGetSymbolAddress((void**)&pF, g_F);
    cudaGetSymbolAddress((void**)&pX, g_x);
    cudaGetSymbolAddress((void**)&pXf, g_xf);
    cudaGetSymbolAddress((void**)&pAgg, g_agg);
    cudaGetSymbolAddress((void**)&pT, g_t);

    ngemm_fn f_plain = hmma_node_gemm<0, 0, 0>;
    ngemm_fn f_ssp   = hmma_node_gemm<0, 1, 0>;
    ngemm_fn f_res   = hmma_node_gemm<0, 0, 1>;
    ngemm_fn f_silu  = hmma_node_gemm<1, 0, 0>;

    cudaFuncSetAttribute((const void*)f_plain, cudaFuncAttributeMaxDynamicSharedMemorySize, NODE_SMEM_BYTES);
    cudaFuncSetAttribute((const void*)f_ssp,   cudaFuncAttributeMaxDynamicSharedMemorySize, NODE_SMEM_BYTES);
    cudaFuncSetAttribute((const void*)f_res,   cudaFuncAttributeMaxDynamicSharedMemorySize, NODE_SMEM_BYTES);
    cudaFuncSetAttribute((const void*)f_silu,  cudaFuncAttributeMaxDynamicSharedMemorySize, NODE_SMEM_BYTES);
    cudaFuncSetAttribute((const void*)edge_kernel, cudaFuncAttributeMaxDynamicSharedMemorySize, EDGE_SMEM_BYTES);

    int nsm = 148;
    cudaDeviceGetAttribute(&nsm, cudaDevAttrMultiProcessorCount, 0);
    const int etiles = (E + 127) / 128;
    const int ntiles = (N + 127) / 128;

    edge_geom<<<(E + 255) / 256, 256>>>(pos, idx_i, idx_j, pD, pRc, E);
    edge_rbf<<<(E * NRBF + 255) / 256, 256>>>(edge_attr, edge_emb, pD, pF, E);
    embed_zero<<<(N * NB + 255) / 256, 256>>>(z, z_res, ele_emb, res_emb, pX, pAgg, out, N, out_size);

    const int nz4 = N * NB / 4;

    for (int it = 0; it < 6; it++) {
        if (it > 0)
            zero_kernel<<<(nz4 + 255) / 256, 256>>>((float4*)pAgg, nz4);
        f_plain<<<nsm, 512, NODE_SMEM_BYTES>>>(
            pX, in2f_W + (size_t)it * NB * NB, nullptr, pX, pXf, N, ntiles);
        edge_kernel<<<nsm, 512, EDGE_SMEM_BYTES>>>(
            idx_i, idx_j,
            filt_W1 + (size_t)it * NRBF * NB, filt_b1 + (size_t)it * NB,
            filt_W2 + (size_t)it * NB * NB,  filt_b2 + (size_t)it * NB,
            pF, pRc, pXf, pAgg, E, etiles);
        f_ssp<<<nsm, 512, NODE_SMEM_BYTES>>>(
            pAgg, f2out_W1 + (size_t)it * NB * NB, f2out_b1 + (size_t)it * NB, pAgg, pT, N, ntiles);
        f_res<<<nsm, 512, NODE_SMEM_BYTES>>>(
            pT, f2out_W2 + (size_t)it * NB * NB, f2out_b2 + (size_t)it * NB, pX, pX, N, ntiles);
    }

    norm_kernel<<<(N + 7) / 8, 256>>>(pX, pT, N);
    f_silu<<<nsm, 512, NODE_SMEM_BYTES>>>(pT, head_W1, head_b1, pT, pXf, N, ntiles);
    head_final<<<(N + 7) / 8, 256>>>(pXf, head_W2, batch, out, N);
}

// round 8
// speedup vs baseline: 5.0421x; 1.7784x over previous
#include <cuda_runtime.h>
#include <cuda_bf16.h>
#include <stdint.h>
#include <math.h>

#define NATOMS 100000
#define NEDGES 1600000
#define NB 128
#define NRBF 32
#define CUTOFF_F 10.0f
#define PI_F 3.14159265358979f
#define LOG2_F 0.69314718055994531f

// ---------------- scratch (static __device__, no allocations) ----------------
__device__ int   g_cnt;
__device__ int   g_ci[NEDGES];
__device__ int   g_cj[NEDGES];
__device__ float g_rc[NEDGES];
__device__ float g_F[(size_t)NEDGES * NRBF];
__device__ float g_x[(size_t)NATOMS * NB];
__device__ float g_xf[(size_t)NATOMS * NB];
__device__ float g_agg[(size_t)NATOMS * NB];
__device__ float g_t[(size_t)NATOMS * NB];

// ---------------- math helpers ----------------
__device__ __forceinline__ float sspf(float v) {
    float ex = __expf(-fabsf(v));
    return fmaxf(v, 0.0f) + __logf(1.0f + ex) - LOG2_F;
}

__device__ __forceinline__ float siluf(float v) {
    return v * (1.0f / (1.0f + __expf(-v)));
}

__device__ __forceinline__ void red_add_v2(float* p, float a, float b) {
    asm volatile("red.global.add.v2.f32 [%0], {%1,%2};"
                 :: "l"(p), "f"(a), "f"(b) : "memory");
}

// HMMA bf16: D(f32) += A(16x16 bf16) * B(16x8 bf16)   [layout validated R5/R6]
__device__ __forceinline__ void mma_bf16(float* c, const uint32_t* a, const uint32_t* b) {
    asm volatile(
        "mma.sync.aligned.m16n8k16.row.col.f32.bf16.bf16.f32 "
        "{%0,%1,%2,%3}, {%4,%5,%6,%7}, {%8,%9}, {%0,%1,%2,%3};"
        : "+f"(c[0]), "+f"(c[1]), "+f"(c[2]), "+f"(c[3])
        : "r"(a[0]), "r"(a[1]), "r"(a[2]), "r"(a[3]), "r"(b[0]), "r"(b[1]));
}

// ---------------- smem byte offsets for edge kernel ----------------
#define SM_B1    0
#define SM_B2    512
#define SM_RC    1024
#define SM_II    1536
#define SM_JJ    2048
#define SM_FHI   2560
#define SM_FLO   12800
#define SM_W1HI  23040
#define SM_W1LO  33280
#define SM_HHI   43520
#define SM_HLO   78336
#define SM_WHI   113152
#define SM_WLO   147968
#define EDGE_SMEM_BYTES 182784

// ---------------- smem byte offsets for node kernel ----------------
#define NSM_B    0
#define NSM_INHI 512
#define NSM_INLO 35328
#define NSM_WHI  70144
#define NSM_WLO  104960
#define NODE_SMEM_BYTES 139776

// ---------------- prep kernels ----------------
__global__ void prep_zero() {
    if (threadIdx.x == 0) g_cnt = 0;
}

// compact edges with d < CUTOFF; write ci/cj/rc and RBF row F for survivors
__global__ void edge_compact(const float* __restrict__ pos,
                             const int* __restrict__ idx_i,
                             const int* __restrict__ idx_j,
                             const int* __restrict__ edge_attr,
                             const float* __restrict__ edge_emb, int E) {
    int e = blockIdx.x * blockDim.x + threadIdx.x;
    int lane = threadIdx.x & 31;
    bool active = false;
    int a = 0, b = 0;
    float dd = 0.f;
    if (e < E) {
        a = idx_i[e]; b = idx_j[e];
        float dx = pos[a * 3 + 0] - pos[b * 3 + 0];
        float dy = pos[a * 3 + 1] - pos[b * 3 + 1];
        float dz = pos[a * 3 + 2] - pos[b * 3 + 2];
        dd = sqrtf(dx * dx + dy * dy + dz * dz);
        active = (dd < CUTOFF_F);
    }
    unsigned mask = __ballot_sync(0xffffffffu, active);
    if (!active) return;
    int leader = __ffs(mask) - 1;
    int rank = __popc(mask & ((1u << lane) - 1));
    int base = 0;
    if (lane == leader) base = atomicAdd(&g_cnt, __popc(mask));
    base = __shfl_sync(mask, base, leader);
    int p = base + rank;

    g_ci[p] = a;
    g_cj[p] = b;
    g_rc[p] = 0.5f * (__cosf(dd * (PI_F / CUTOFF_F)) + 1.0f);

    const float width = CUTOFF_F / 31.0f;
    const float coeff = -0.5f / (width * width);
    const float* emb = edge_emb + edge_attr[e] * NRBF;
    float4* dst = (float4*)(g_F + (size_t)p * NRBF);
#pragma unroll
    for (int j = 0; j < 8; j++) {
        float4 v;
        float u0 = dd - (float)(4 * j + 0) * width;
        float u1 = dd - (float)(4 * j + 1) * width;
        float u2 = dd - (float)(4 * j + 2) * width;
        float u3 = dd - (float)(4 * j + 3) * width;
        v.x = __expf(coeff * u0 * u0) + emb[4 * j + 0];
        v.y = __expf(coeff * u1 * u1) + emb[4 * j + 1];
        v.z = __expf(coeff * u2 * u2) + emb[4 * j + 2];
        v.w = __expf(coeff * u3 * u3) + emb[4 * j + 3];
        dst[j] = v;
    }
}

__global__ void embed_zero(const int* __restrict__ z, const int* __restrict__ z_res,
                           const float* __restrict__ ele_emb, const float* __restrict__ res_emb,
                           float* __restrict__ x, float* __restrict__ agg,
                           float* __restrict__ outbuf, int N, int out_n) {
    int t = blockIdx.x * blockDim.x + threadIdx.x;
    if (t < out_n) outbuf[t] = 0.f;
    if (t >= N * NB) return;
    int n = t >> 7, c = t & 127;
    agg[t] = 0.f;
    x[t] = ele_emb[z[n] * NB + c] + res_emb[z_res[n] * NB + c];
}

// ---------------- persistent HMMA node GEMM ----------------
template <int PRE, int POST, int RES>
__global__ __launch_bounds__(512, 1) void hmma_node_gemm(
    const float* __restrict__ in, const float* __restrict__ W,
    const float* __restrict__ bias, const float* __restrict__ res,
    float* __restrict__ out, float* __restrict__ zbuf, int M, int ntiles)
{
    extern __shared__ char smch[];
    float* sB = (float*)(smch + NSM_B);

    const int t = threadIdx.x;
    const int wid = t >> 5;
    const int lane = t & 31;
    const int q = lane & 3;
    const int lr = lane >> 2;

    if (t < 128) sB[t] = bias ? bias[t] : 0.f;
#pragma unroll
    for (int i = 0; i < 8; i++) {
        int idx4 = i * 512 + t;
        int k = idx4 >> 5;
        int n0 = (idx4 & 31) * 4;
        float4 w = ((const float4*)W)[idx4];
        float vs[4] = { w.x, w.y, w.z, w.w };
#pragma unroll
        for (int d = 0; d < 4; d++) {
            __nv_bfloat16 hi = __float2bfloat16(vs[d]);
            __nv_bfloat16 lo = __float2bfloat16(vs[d] - __bfloat162float(hi));
            size_t off = ((size_t)(n0 + d) * 136 + k) * 2;
            *(__nv_bfloat16*)(smch + NSM_WHI + off) = hi;
            *(__nv_bfloat16*)(smch + NSM_WLO + off) = lo;
        }
    }
    __syncthreads();

    const int mg = wid & 3;
    const int ng = wid >> 2;

    for (int tile = blockIdx.x; tile < ntiles; tile += gridDim.x) {
        const int m0 = tile * 128;

        {
            int r = t >> 2, cq = (t & 3) * 32;
            const float4* src = (const float4*)(in + (size_t)(m0 + r) * NB + cq);
            bool ok = (m0 + r < M);
#pragma unroll
            for (int j = 0; j < 8; j++) {
                float4 f = ok ? src[j] : make_float4(0.f, 0.f, 0.f, 0.f);
                if (PRE == 1) { f.x = siluf(f.x); f.y = siluf(f.y); f.z = siluf(f.z); f.w = siluf(f.w); }
                __nv_bfloat162 h0 = __floats2bfloat162_rn(f.x, f.y);
                __nv_bfloat162 h1 = __floats2bfloat162_rn(f.z, f.w);
                __nv_bfloat162 l0 = __floats2bfloat162_rn(f.x - __bfloat162float(h0.x), f.y - __bfloat162float(h0.y));
                __nv_bfloat162 l1 = __floats2bfloat162_rn(f.z - __bfloat162float(h1.x), f.w - __bfloat162float(h1.y));
                size_t off = ((size_t)r * 136 + cq + j * 4) * 2;
                *(uint2*)(smch + NSM_INHI + off) = make_uint2(*(uint32_t*)&h0, *(uint32_t*)&h1);
                *(uint2*)(smch + NSM_INLO + off) = make_uint2(*(uint32_t*)&l0, *(uint32_t*)&l1);
            }
        }
        __syncthreads();

        float acc[2][4][4];
#pragma unroll
        for (int mt = 0; mt < 2; mt++)
#pragma unroll
            for (int nt = 0; nt < 4; nt++)
#pragma unroll
                for (int v = 0; v < 4; v++) acc[mt][nt][v] = 0.f;

#pragma unroll 2
        for (int ks = 0; ks < 8; ks++) {
            const int k0 = ks * 16;
            uint32_t ahi[2][4], alo[2][4], bhi[4][2], blo[4][2];
#pragma unroll
            for (int mt = 0; mt < 2; mt++) {
                int m = mg * 32 + mt * 16 + lr;
                size_t o0 = ((size_t)m * 136 + k0 + 2 * q) * 2;
                size_t o1 = ((size_t)(m + 8) * 136 + k0 + 2 * q) * 2;
                ahi[mt][0] = *(const uint32_t*)(smch + NSM_INHI + o0);
                ahi[mt][1] = *(const uint32_t*)(smch + NSM_INHI + o1);
                ahi[mt][2] = *(const uint32_t*)(smch + NSM_INHI + o0 + 16);
                ahi[mt][3] = *(const uint32_t*)(smch + NSM_INHI + o1 + 16);
                alo[mt][0] = *(const uint32_t*)(smch + NSM_INLO + o0);
                alo[mt][1] = *(const uint32_t*)(smch + NSM_INLO + o1);
                alo[mt][2] = *(const uint32_t*)(smch + NSM_INLO + o0 + 16);
                alo[mt][3] = *(const uint32_t*)(smch + NSM_INLO + o1 + 16);
            }
#pragma unroll
            for (int nt = 0; nt < 4; nt++) {
                int n = ng * 32 + nt * 8 + lr;
                size_t ob = ((size_t)n * 136 + k0 + 2 * q) * 2;
                bhi[nt][0] = *(const uint32_t*)(smch + NSM_WHI + ob);
                bhi[nt][1] = *(const uint32_t*)(smch + NSM_WHI + ob + 16);
                blo[nt][0] = *(const uint32_t*)(smch + NSM_WLO + ob);
                blo[nt][1] = *(const uint32_t*)(smch + NSM_WLO + ob + 16);
            }
#pragma unroll
            for (int mt = 0; mt < 2; mt++) {
#pragma unroll
                for (int nt = 0; nt < 4; nt++) {
                    mma_bf16(acc[mt][nt], ahi[mt], bhi[nt]);
                    mma_bf16(acc[mt][nt], ahi[mt], blo[nt]);
                    mma_bf16(acc[mt][nt], alo[mt], bhi[nt]);
                }
            }
        }

#pragma unroll
        for (int mt = 0; mt < 2; mt++) {
#pragma unroll
            for (int half = 0; half < 2; half++) {
                int rr = mg * 32 + mt * 16 + lr + 8 * half;
                int m = m0 + rr;
                if (m < M) {
                    const float* rrow = res + (size_t)m * NB;
                    float* orow = out + (size_t)m * NB;
                    float* zrow = zbuf ? zbuf + (size_t)m * NB : 0;
#pragma unroll
                    for (int nt = 0; nt < 4; nt++) {
                        int c = ng * 32 + nt * 8 + 2 * q;
                        float2 bv = *(const float2*)&sB[c];
                        float v0 = acc[mt][nt][2 * half]     + bv.x;
                        float v1 = acc[mt][nt][2 * half + 1] + bv.y;
                        if (POST == 1) { v0 = sspf(v0); v1 = sspf(v1); }
                        if (RES == 1) {
                            float2 rv = *(const float2*)(rrow + c);
                            v0 += rv.x; v1 += rv.y;
                        }
                        *(float2*)(orow + c) = make_float2(v0, v1);
                        if (zbuf) *(float2*)(zrow + c) = make_float2(0.f, 0.f);
                    }
                }
            }
        }
        __syncthreads();
    }
}

// ---------------- persistent fused edge kernel (compacted edges) ----------------
__global__ __launch_bounds__(512, 1) void edge_kernel(
    const int* __restrict__ ci, const int* __restrict__ cj,
    const float* __restrict__ W1, const float* __restrict__ b1,
    const float* __restrict__ W2, const float* __restrict__ b2,
    const float* __restrict__ Ff, const float* __restrict__ rcut,
    const float* __restrict__ xf, float* __restrict__ agg,
    const int* __restrict__ cntPtr)
{
    extern __shared__ char smch[];
    float* sB1 = (float*)(smch + SM_B1);
    float* sB2 = (float*)(smch + SM_B2);
    float* sRC = (float*)(smch + SM_RC);
    int*   sII = (int*)(smch + SM_II);
    int*   sJJ = (int*)(smch + SM_JJ);

    const int E = *cntPtr;
    const int ntiles = (E + 127) >> 7;

    const int t = threadIdx.x;
    const int wid = t >> 5;
    const int lane = t & 31;
    const int q = lane & 3;
    const int lr = lane >> 2;

    if (t < 128) { sB1[t] = b1[t]; sB2[t] = b2[t]; }
#pragma unroll
    for (int i = 0; i < 2; i++) {
        int idx4 = i * 512 + t;
        int k = idx4 >> 5;
        int n0 = (idx4 & 31) * 4;
        float4 w = ((const float4*)W1)[idx4];
        float vs[4] = { w.x, w.y, w.z, w.w };
#pragma unroll
        for (int d = 0; d < 4; d++) {
            __nv_bfloat16 hi = __float2bfloat16(vs[d]);
            __nv_bfloat16 lo = __float2bfloat16(vs[d] - __bfloat162float(hi));
            size_t off = ((size_t)(n0 + d) * 40 + k) * 2;
            *(__nv_bfloat16*)(smch + SM_W1HI + off) = hi;
            *(__nv_bfloat16*)(smch + SM_W1LO + off) = lo;
        }
    }
#pragma unroll
    for (int i = 0; i < 8; i++) {
        int idx4 = i * 512 + t;
        int k = idx4 >> 5;
        int n0 = (idx4 & 31) * 4;
        float4 w = ((const float4*)W2)[idx4];
        float vs[4] = { w.x, w.y, w.z, w.w };
#pragma unroll
        for (int d = 0; d < 4; d++) {
            __nv_bfloat16 hi = __float2bfloat16(vs[d]);
            __nv_bfloat16 lo = __float2bfloat16(vs[d] - __bfloat162float(hi));
            size_t off = ((size_t)(n0 + d) * 136 + k) * 2;
            *(__nv_bfloat16*)(smch + SM_WHI + off) = hi;
            *(__nv_bfloat16*)(smch + SM_WLO + off) = lo;
        }
    }

    for (int tile = blockIdx.x; tile < ntiles; tile += gridDim.x) {
        const int eb = tile * 128;

        {
            int r = t >> 2, kq = (t & 3) * 8;
            float4 f0 = make_float4(0.f, 0.f, 0.f, 0.f);
            float4 f1 = make_float4(0.f, 0.f, 0.f, 0.f);
            if (eb + r < E) {
                const float4* src = (const float4*)(Ff + (size_t)(eb + r) * NRBF + kq);
                f0 = src[0]; f1 = src[1];
            }
            __nv_bfloat162 h0 = __floats2bfloat162_rn(f0.x, f0.y);
            __nv_bfloat162 h1 = __floats2bfloat162_rn(f0.z, f0.w);
            __nv_bfloat162 h2 = __floats2bfloat162_rn(f1.x, f1.y);
            __nv_bfloat162 h3 = __floats2bfloat162_rn(f1.z, f1.w);
            __nv_bfloat162 l0 = __floats2bfloat162_rn(f0.x - __bfloat162float(h0.x), f0.y - __bfloat162float(h0.y));
            __nv_bfloat162 l1 = __floats2bfloat162_rn(f0.z - __bfloat162float(h1.x), f0.w - __bfloat162float(h1.y));
            __nv_bfloat162 l2 = __floats2bfloat162_rn(f1.x - __bfloat162float(h2.x), f1.y - __bfloat162float(h2.y));
            __nv_bfloat162 l3 = __floats2bfloat162_rn(f1.z - __bfloat162float(h3.x), f1.w - __bfloat162float(h3.y));
            size_t off = ((size_t)r * 40 + kq) * 2;
            uint4 uh = make_uint4(*(uint32_t*)&h0, *(uint32_t*)&h1, *(uint32_t*)&h2, *(uint32_t*)&h3);
            uint4 ul = make_uint4(*(uint32_t*)&l0, *(uint32_t*)&l1, *(uint32_t*)&l2, *(uint32_t*)&l3);
            *(uint4*)(smch + SM_FHI + off) = uh;
            *(uint4*)(smch + SM_FLO + off) = ul;
        }
        if (t < 128) {
            int e = eb + t;
            float rcv = 0.f; int iiv = 0, jjv = 0;
            if (e < E) { rcv = rcut[e]; iiv = ci[e]; jjv = cj[e]; }
            sRC[t] = rcv; sII[t] = iiv; sJJ[t] = jjv;
        }
        __syncthreads();

        {
            const int pm = wid & 7, pn = wid >> 3;
            const int m0 = pm * 16, n0 = pn * 64;
            uint32_t ahi[2][4], alo[2][4];
#pragma unroll
            for (int ks = 0; ks < 2; ks++) {
                size_t o0 = ((size_t)(m0 + lr) * 40 + ks * 16 + 2 * q) * 2;
                size_t o1 = o0 + 640;
                ahi[ks][0] = *(const uint32_t*)(smch + SM_FHI + o0);
                ahi[ks][1] = *(const uint32_t*)(smch + SM_FHI + o1);
                ahi[ks][2] = *(const uint32_t*)(smch + SM_FHI + o0 + 16);
                ahi[ks][3] = *(const uint32_t*)(smch + SM_FHI + o1 + 16);
                alo[ks][0] = *(const uint32_t*)(smch + SM_FLO + o0);
                alo[ks][1] = *(const uint32_t*)(smch + SM_FLO + o1);
                alo[ks][2] = *(const uint32_t*)(smch + SM_FLO + o0 + 16);
                alo[ks][3] = *(const uint32_t*)(smch + SM_FLO + o1 + 16);
            }
#pragma unroll
            for (int nt = 0; nt < 8; nt++) {
                int n = n0 + nt * 8 + lr;
                float c[4] = { 0.f, 0.f, 0.f, 0.f };
#pragma unroll
                for (int ks = 0; ks < 2; ks++) {
                    size_t ob = ((size_t)n * 40 + ks * 16 + 2 * q) * 2;
                    uint32_t bh[2] = { *(const uint32_t*)(smch + SM_W1HI + ob),
                                       *(const uint32_t*)(smch + SM_W1HI + ob + 16) };
                    uint32_t bl[2] = { *(const uint32_t*)(smch + SM_W1LO + ob),
                                       *(const uint32_t*)(smch + SM_W1LO + ob + 16) };
                    mma_bf16(c, ahi[ks], bh);
                    mma_bf16(c, ahi[ks], bl);
                    mma_bf16(c, alo[ks], bh);
                }
                int cc = n0 + nt * 8 + 2 * q;
                float2 bv = *(const float2*)&sB1[cc];
                float h00 = sspf(c[0] + bv.x), h01 = sspf(c[1] + bv.y);
                float h10 = sspf(c[2] + bv.x), h11 = sspf(c[3] + bv.y);
                __nv_bfloat162 p0 = __floats2bfloat162_rn(h00, h01);
                __nv_bfloat162 p1 = __floats2bfloat162_rn(h10, h11);
                __nv_bfloat162 e0 = __floats2bfloat162_rn(h00 - __bfloat162float(p0.x), h01 - __bfloat162float(p0.y));
                __nv_bfloat162 e1 = __floats2bfloat162_rn(h10 - __bfloat162float(p1.x), h11 - __bfloat162float(p1.y));
                size_t oh0 = ((size_t)(m0 + lr) * 136 + cc) * 2;
                size_t oh1 = oh0 + 136 * 8 * 2;
                *(uint32_t*)(smch + SM_HHI + oh0) = *(uint32_t*)&p0;
                *(uint32_t*)(smch + SM_HHI + oh1) = *(uint32_t*)&p1;
                *(uint32_t*)(smch + SM_HLO + oh0) = *(uint32_t*)&e0;
                *(uint32_t*)(smch + SM_HLO + oh1) = *(uint32_t*)&e1;
            }
        }
        __syncthreads();

        {
            const int mg = wid & 3;
            const int ng = wid >> 2;

            float acc[2][4][4];
#pragma unroll
            for (int mt = 0; mt < 2; mt++)
#pragma unroll
                for (int nt = 0; nt < 4; nt++)
#pragma unroll
                    for (int v = 0; v < 4; v++) acc[mt][nt][v] = 0.f;

#pragma unroll 2
            for (int ks = 0; ks < 8; ks++) {
                const int k0 = ks * 16;
                uint32_t ahi[2][4], alo[2][4], bhi[4][2], blo[4][2];
#pragma unroll
                for (int mt = 0; mt < 2; mt++) {
                    int m = mg * 32 + mt * 16 + lr;
                    size_t o0 = ((size_t)m * 136 + k0 + 2 * q) * 2;
                    size_t o1 = ((size_t)(m + 8) * 136 + k0 + 2 * q) * 2;
                    ahi[mt][0] = *(const uint32_t*)(smch + SM_HHI + o0);
                    ahi[mt][1] = *(const uint32_t*)(smch + SM_HHI + o1);
                    ahi[mt][2] = *(const uint32_t*)(smch + SM_HHI + o0 + 16);
                    ahi[mt][3] = *(const uint32_t*)(smch + SM_HHI + o1 + 16);
                    alo[mt][0] = *(const uint32_t*)(smch + SM_HLO + o0);
                    alo[mt][1] = *(const uint32_t*)(smch + SM_HLO + o1);
                    alo[mt][2] = *(const uint32_t*)(smch + SM_HLO + o0 + 16);
                    alo[mt][3] = *(const uint32_t*)(smch + SM_HLO + o1 + 16);
                }
#pragma unroll
                for (int nt = 0; nt < 4; nt++) {
                    int n = ng * 32 + nt * 8 + lr;
                    size_t ob = ((size_t)n * 136 + k0 + 2 * q) * 2;
                    bhi[nt][0] = *(const uint32_t*)(smch + SM_WHI + ob);
                    bhi[nt][1] = *(const uint32_t*)(smch + SM_WHI + ob + 16);
                    blo[nt][0] = *(const uint32_t*)(smch + SM_WLO + ob);
                    blo[nt][1] = *(const uint32_t*)(smch + SM_WLO + ob + 16);
                }
#pragma unroll
                for (int mt = 0; mt < 2; mt++) {
#pragma unroll
                    for (int nt = 0; nt < 4; nt++) {
                        mma_bf16(acc[mt][nt], ahi[mt], bhi[nt]);
                        mma_bf16(acc[mt][nt], ahi[mt], blo[nt]);
                        mma_bf16(acc[mt][nt], alo[mt], bhi[nt]);
                    }
                }
            }

#pragma unroll
            for (int mt = 0; mt < 2; mt++) {
#pragma unroll
                for (int half = 0; half < 2; half++) {
                    int r = mg * 32 + mt * 16 + lr + 8 * half;
                    float rc = sRC[r];
                    int ii = sII[r], jj = sJJ[r];
                    const float* xrow = xf + (size_t)jj * NB;
                    float* arow = agg + (size_t)ii * NB;
#pragma unroll
                    for (int nt = 0; nt < 4; nt++) {
                        int c = ng * 32 + nt * 8 + 2 * q;
                        float2 xv = *(const float2*)(xrow + c);
                        float2 bv = *(const float2*)&sB2[c];
                        float v0 = (acc[mt][nt][2 * half]     + bv.x) * rc * xv.x;
                        float v1 = (acc[mt][nt][2 * half + 1] + bv.y) * rc * xv.y;
                        red_add_v2(arow + c, v0, v1);
                    }
                }
            }
        }
        __syncthreads();
    }
}

// ---------------- head ----------------
__global__ void norm_kernel(const float* __restrict__ x, float* __restrict__ o, int M) {
    int w = (blockIdx.x * blockDim.x + threadIdx.x) >> 5;
    int lane = threadIdx.x & 31;
    if (w >= M) return;
    float4 v = ((const float4*)(x + (size_t)w * NB))[lane];
    float s = v.x * v.x + v.y * v.y + v.z * v.z + v.w * v.w;
#pragma unroll
    for (int o2 = 16; o2 > 0; o2 >>= 1) s += __shfl_xor_sync(0xffffffffu, s, o2);
    float scale = 1.0f / fmaxf(sqrtf(s), 1e-12f);
    ((float4*)(o + (size_t)w * NB))[lane] =
        make_float4(v.x * scale, v.y * scale, v.z * scale, v.w * scale);
}

__global__ void head_final(const float* __restrict__ h, const float* __restrict__ w2,
                           const int* __restrict__ batch, float* __restrict__ out, int M) {
    int w = (blockIdx.x * blockDim.x + threadIdx.x) >> 5;
    int lane = threadIdx.x & 31;
    if (w >= M) return;
    float4 v = ((const float4*)(h + (size_t)w * NB))[lane];
    float4 ww = ((const float4*)w2)[lane];
    float s = siluf(v.x) * ww.x + siluf(v.y) * ww.y + siluf(v.z) * ww.z + siluf(v.w) * ww.w;
#pragma unroll
    for (int o2 = 16; o2 > 0; o2 >>= 1) s += __shfl_xor_sync(0xffffffffu, s, o2);
    if (lane == 0) atomicAdd(&out[batch[w]], s);
}

// ---------------- launch ----------------
typedef void (*ngemm_fn)(const float*, const float*, const float*, const float*, float*, float*, int, int);

extern "C" void kernel_launch(void* const* d_in, const int* in_sizes, int n_in,
                              void* d_out, int out_size)
{
    const int*   z         = (const int*)d_in[0];
    const int*   z_res     = (const int*)d_in[1];
    const float* pos       = (const float*)d_in[2];
    const int*   idx_i     = (const int*)d_in[3];
    const int*   idx_j     = (const int*)d_in[4];
    const int*   edge_attr = (const int*)d_in[5];
    const int*   batch     = (const int*)d_in[6];
    const float* ele_emb   = (const float*)d_in[7];
    const float* res_emb   = (const float*)d_in[8];
    const float* edge_emb  = (const float*)d_in[9];
    const float* in2f_W    = (const float*)d_in[10];
    const float* filt_W1   = (const float*)d_in[11];
    const float* filt_b1   = (const float*)d_in[12];
    const float* filt_W2   = (const float*)d_in[13];
    const float* filt_b2   = (const float*)d_in[14];
    const float* f2out_W1  = (const float*)d_in[15];
    const float* f2out_b1  = (const float*)d_in[16];
    const float* f2out_W2  = (const float*)d_in[17];
    const float* f2out_b2  = (const float*)d_in[18];
    const float* head_W1   = (const float*)d_in[19];
    const float* head_b1   = (const float*)d_in[20];
    const float* head_W2   = (const float*)d_in[21];
    float* out = (float*)d_out;

    const int N = in_sizes[0];
    const int E = in_sizes[3];

    int *pCnt, *pCi, *pCj;
    float *pRc, *pF, *pX, *pXf, *pAgg, *pT;
    cudaGetSymbolAddress((void**)&pCnt, g_cnt);
    cudaGetSymbolAddress((void**)&pCi, g_ci);
    cudaGetSymbolAddress((void**)&pCj, g_cj);
    cudaGetSymbolAddress((void**)&pRc, g_rc);
    cudaGetSymbolAddress((void**)&pF, g_F);
    cudaGetSymbolAddress((void**)&pX, g_x);
    cudaGetSymbolAddress((void**)&pXf, g_xf);
    cudaGetSymbolAddress((void**)&pAgg, g_agg);
    cudaGetSymbolAddress((void**)&pT, g_t);

    ngemm_fn f_plain = hmma_node_gemm<0, 0, 0>;
    ngemm_fn f_ssp   = hmma_node_gemm<0, 1, 0>;
    ngemm_fn f_res   = hmma_node_gemm<0, 0, 1>;
    ngemm_fn f_silu  = hmma_node_gemm<1, 0, 0>;

    cudaFuncSetAttribute((const void*)f_plain, cudaFuncAttributeMaxDynamicSharedMemorySize, NODE_SMEM_BYTES);
    cudaFuncSetAttribute((const void*)f_ssp,   cudaFuncAttributeMaxDynamicSharedMemorySize, NODE_SMEM_BYTES);
    cudaFuncSetAttribute((const void*)f_res,   cudaFuncAttributeMaxDynamicSharedMemorySize, NODE_SMEM_BYTES);
    cudaFuncSetAttribute((const void*)f_silu,  cudaFuncAttributeMaxDynamicSharedMemorySize, NODE_SMEM_BYTES);
    cudaFuncSetAttribute((const void*)edge_kernel, cudaFuncAttributeMaxDynamicSharedMemorySize, EDGE_SMEM_BYTES);

    int nsm = 148;
    cudaDeviceGetAttribute(&nsm, cudaDevAttrMultiProcessorCount, 0);
    const int ntiles = (N + 127) / 128;

    prep_zero<<<1, 32>>>();
    edge_compact<<<(E + 255) / 256, 256>>>(pos, idx_i, idx_j, edge_attr, edge_emb, E);
    embed_zero<<<(N * NB + 255) / 256, 256>>>(z, z_res, ele_emb, res_emb, pX, pAgg, out, N, out_size);

    for (int it = 0; it < 6; it++) {
        f_plain<<<nsm, 512, NODE_SMEM_BYTES>>>(
            pX, in2f_W + (size_t)it * NB * NB, nullptr, pX, pXf, nullptr, N, ntiles);
        edge_kernel<<<nsm, 512, EDGE_SMEM_BYTES>>>(
            pCi, pCj,
            filt_W1 + (size_t)it * NRBF * NB, filt_b1 + (size_t)it * NB,
            filt_W2 + (size_t)it * NB * NB,  filt_b2 + (size_t)it * NB,
            pF, pRc, pXf, pAgg, pCnt);
        f_ssp<<<nsm, 512, NODE_SMEM_BYTES>>>(
            pAgg, f2out_W1 + (size_t)it * NB * NB, f2out_b1 + (size_t)it * NB, pAgg, pT, nullptr, N, ntiles);
        f_res<<<nsm, 512, NODE_SMEM_BYTES>>>(
            pT, f2out_W2 + (size_t)it * NB * NB, f2out_b2 + (size_t)it * NB, pX, pX,
            (it < 5) ? pAgg : nullptr, N, ntiles);
    }

    norm_kernel<<<(N + 7) / 8, 256>>>(pX, pT, N);
    f_silu<<<nsm, 512, NODE_SMEM_BYTES>>>(pT, head_W1, head_b1, pT, pXf, nullptr, N, ntiles);
    head_final<<<(N + 7) / 8, 256>>>(pXf, head_W2, batch, out, N);
}

// round 9
// speedup vs baseline: 5.0579x; 1.0031x over previous
#include <cuda_runtime.h>
#include <cuda_bf16.h>
#include <stdint.h>
#include <math.h>

#define NATOMS 100000
#define NEDGES 1600000
#define NB 128
#define NRBF 32
#define CUTOFF_F 10.0f
#define PI_F 3.14159265358979f
#define LOG2_F 0.69314718055994531f

// ---------------- scratch (static __device__, no allocations) ----------------
__device__ int   g_cnt;
__device__ int   g_ci[NEDGES];
__device__ int   g_cj[NEDGES];
__device__ float g_rc[NEDGES];
__device__ float g_F[(size_t)NEDGES * NRBF];
__device__ float g_x[(size_t)NATOMS * NB];
__device__ float g_xf[(size_t)NATOMS * NB];
__device__ float g_agg[(size_t)NATOMS * NB];

// ---------------- math helpers ----------------
__device__ __forceinline__ float sspf(float v) {
    float ex = __expf(-fabsf(v));
    return fmaxf(v, 0.0f) + __logf(1.0f + ex) - LOG2_F;
}

__device__ __forceinline__ float siluf(float v) {
    return v * (1.0f / (1.0f + __expf(-v)));
}

__device__ __forceinline__ void red_add_v2(float* p, float a, float b) {
    asm volatile("red.global.add.v2.f32 [%0], {%1,%2};"
                 :: "l"(p), "f"(a), "f"(b) : "memory");
}

// HMMA bf16: D(f32) += A(16x16 bf16) * B(16x8 bf16)   [layout validated R5/R6]
__device__ __forceinline__ void mma_bf16(float* c, const uint32_t* a, const uint32_t* b) {
    asm volatile(
        "mma.sync.aligned.m16n8k16.row.col.f32.bf16.bf16.f32 "
        "{%0,%1,%2,%3}, {%4,%5,%6,%7}, {%8,%9}, {%0,%1,%2,%3};"
        : "+f"(c[0]), "+f"(c[1]), "+f"(c[2]), "+f"(c[3])
        : "r"(a[0]), "r"(a[1]), "r"(a[2]), "r"(a[3]), "r"(b[0]), "r"(b[1]));
}

// split float -> bf16 hi/lo
__device__ __forceinline__ void bf16_split(float v, __nv_bfloat16& hi, __nv_bfloat16& lo) {
    hi = __float2bfloat16(v);
    lo = __float2bfloat16(v - __bfloat162float(hi));
}

// ---------------- smem byte offsets for edge kernel ----------------
#define SM_B1    0
#define SM_B2    512
#define SM_RC    1024
#define SM_II    1536
#define SM_JJ    2048
#define SM_FHI   2560
#define SM_FLO   12800
#define SM_W1HI  23040
#define SM_W1LO  33280
#define SM_HHI   43520
#define SM_HLO   78336
#define SM_WHI   113152
#define SM_WLO   147968
#define EDGE_SMEM_BYTES 182784

// ---------------- smem byte offsets for node gemm kernel ----------------
#define NSM_B    0
#define NSM_INHI 512
#define NSM_INLO 35328
#define NSM_WHI  70144
#define NSM_WLO  104960
#define NODE_SMEM_BYTES 139776

// ---------------- smem byte offsets for fused f2out kernel ----------------
#define N2_B1    0
#define N2_B2    512
#define N2_INHI  1024
#define N2_INLO  35840
#define N2_W1HI  70656
#define N2_W1LO  105472
#define N2_W2HI  140288
#define N2_W2LO  175104
#define NODE2_SMEM_BYTES 209920

// ---------------- prep kernels ----------------
__global__ void prep_zero() {
    if (threadIdx.x == 0) g_cnt = 0;
}

__global__ void edge_compact(const float* __restrict__ pos,
                             const int* __restrict__ idx_i,
                             const int* __restrict__ idx_j,
                             const int* __restrict__ edge_attr,
                             const float* __restrict__ edge_emb, int E) {
    int e = blockIdx.x * blockDim.x + threadIdx.x;
    int lane = threadIdx.x & 31;
    bool active = false;
    int a = 0, b = 0;
    float dd = 0.f;
    if (e < E) {
        a = idx_i[e]; b = idx_j[e];
        float dx = pos[a * 3 + 0] - pos[b * 3 + 0];
        float dy = pos[a * 3 + 1] - pos[b * 3 + 1];
        float dz = pos[a * 3 + 2] - pos[b * 3 + 2];
        dd = sqrtf(dx * dx + dy * dy + dz * dz);
        active = (dd < CUTOFF_F);
    }
    unsigned mask = __ballot_sync(0xffffffffu, active);
    if (!active) return;
    int leader = __ffs(mask) - 1;
    int rank = __popc(mask & ((1u << lane) - 1));
    int base = 0;
    if (lane == leader) base = atomicAdd(&g_cnt, __popc(mask));
    base = __shfl_sync(mask, base, leader);
    int p = base + rank;

    g_ci[p] = a;
    g_cj[p] = b;
    g_rc[p] = 0.5f * (__cosf(dd * (PI_F / CUTOFF_F)) + 1.0f);

    const float width = CUTOFF_F / 31.0f;
    const float coeff = -0.5f / (width * width);
    const float* emb = edge_emb + edge_attr[e] * NRBF;
    float4* dst = (float4*)(g_F + (size_t)p * NRBF);
#pragma unroll
    for (int j = 0; j < 8; j++) {
        float4 v;
        float u0 = dd - (float)(4 * j + 0) * width;
        float u1 = dd - (float)(4 * j + 1) * width;
        float u2 = dd - (float)(4 * j + 2) * width;
        float u3 = dd - (float)(4 * j + 3) * width;
        v.x = __expf(coeff * u0 * u0) + emb[4 * j + 0];
        v.y = __expf(coeff * u1 * u1) + emb[4 * j + 1];
        v.z = __expf(coeff * u2 * u2) + emb[4 * j + 2];
        v.w = __expf(coeff * u3 * u3) + emb[4 * j + 3];
        dst[j] = v;
    }
}

__global__ void embed_zero(const int* __restrict__ z, const int* __restrict__ z_res,
                           const float* __restrict__ ele_emb, const float* __restrict__ res_emb,
                           float* __restrict__ x, float* __restrict__ agg,
                           float* __restrict__ outbuf, int N, int out_n) {
    int t = blockIdx.x * blockDim.x + threadIdx.x;
    if (t < out_n) outbuf[t] = 0.f;
    if (t >= N * NB) return;
    int n = t >> 7, c = t & 127;
    agg[t] = 0.f;
    x[t] = ele_emb[z[n] * NB + c] + res_emb[z_res[n] * NB + c];
}

// ---------------- persistent HMMA node GEMM (single GEMM variants) ----------------
// PRE: 0=none, 1=silu, 2=L2-normalize then silu
template <int PRE>
__global__ __launch_bounds__(512, 1) void hmma_node_gemm(
    const float* __restrict__ in, const float* __restrict__ W,
    const float* __restrict__ bias,
    float* __restrict__ out, int M, int ntiles)
{
    extern __shared__ char smch[];
    float* sB = (float*)(smch + NSM_B);

    const int t = threadIdx.x;
    const int wid = t >> 5;
    const int lane = t & 31;
    const int q = lane & 3;
    const int lr = lane >> 2;

    if (t < 128) sB[t] = bias ? bias[t] : 0.f;
#pragma unroll
    for (int i = 0; i < 8; i++) {
        int idx4 = i * 512 + t;
        int k = idx4 >> 5;
        int n0 = (idx4 & 31) * 4;
        float4 w = ((const float4*)W)[idx4];
        float vs[4] = { w.x, w.y, w.z, w.w };
#pragma unroll
        for (int d = 0; d < 4; d++) {
            __nv_bfloat16 hi, lo;
            bf16_split(vs[d], hi, lo);
            size_t off = ((size_t)(n0 + d) * 136 + k) * 2;
            *(__nv_bfloat16*)(smch + NSM_WHI + off) = hi;
            *(__nv_bfloat16*)(smch + NSM_WLO + off) = lo;
        }
    }
    __syncthreads();

    const int mg = wid & 3;
    const int ng = wid >> 2;

    for (int tile = blockIdx.x; tile < ntiles; tile += gridDim.x) {
        const int m0 = tile * 128;

        {
            int r = t >> 2, cq = (t & 3) * 32;
            const float4* src = (const float4*)(in + (size_t)(m0 + r) * NB + cq);
            bool ok = (m0 + r < M);
            float4 fv[8];
#pragma unroll
            for (int j = 0; j < 8; j++)
                fv[j] = ok ? src[j] : make_float4(0.f, 0.f, 0.f, 0.f);
            float scale = 1.0f;
            if (PRE == 2) {
                float ss = 0.f;
#pragma unroll
                for (int j = 0; j < 8; j++)
                    ss += fv[j].x * fv[j].x + fv[j].y * fv[j].y + fv[j].z * fv[j].z + fv[j].w * fv[j].w;
                ss += __shfl_xor_sync(0xffffffffu, ss, 1);
                ss += __shfl_xor_sync(0xffffffffu, ss, 2);
                scale = 1.0f / fmaxf(sqrtf(ss), 1e-12f);
            }
#pragma unroll
            for (int j = 0; j < 8; j++) {
                float4 f = fv[j];
                if (PRE == 2) { f.x *= scale; f.y *= scale; f.z *= scale; f.w *= scale; }
                if (PRE >= 1) { f.x = siluf(f.x); f.y = siluf(f.y); f.z = siluf(f.z); f.w = siluf(f.w); }
                __nv_bfloat162 h0, h1, l0, l1;
                bf16_split(f.x, h0.x, l0.x); bf16_split(f.y, h0.y, l0.y);
                bf16_split(f.z, h1.x, l1.x); bf16_split(f.w, h1.y, l1.y);
                size_t off = ((size_t)r * 136 + cq + j * 4) * 2;
                *(uint2*)(smch + NSM_INHI + off) = make_uint2(*(uint32_t*)&h0, *(uint32_t*)&h1);
                *(uint2*)(smch + NSM_INLO + off) = make_uint2(*(uint32_t*)&l0, *(uint32_t*)&l1);
            }
        }
        __syncthreads();

        float acc[2][4][4];
#pragma unroll
        for (int mt = 0; mt < 2; mt++)
#pragma unroll
            for (int nt = 0; nt < 4; nt++)
#pragma unroll
                for (int v = 0; v < 4; v++) acc[mt][nt][v] = 0.f;

#pragma unroll 2
        for (int ks = 0; ks < 8; ks++) {
            const int k0 = ks * 16;
            uint32_t ahi[2][4], alo[2][4], bhi[4][2], blo[4][2];
#pragma unroll
            for (int mt = 0; mt < 2; mt++) {
                int m = mg * 32 + mt * 16 + lr;
                size_t o0 = ((size_t)m * 136 + k0 + 2 * q) * 2;
                size_t o1 = ((size_t)(m + 8) * 136 + k0 + 2 * q) * 2;
                ahi[mt][0] = *(const uint32_t*)(smch + NSM_INHI + o0);
                ahi[mt][1] = *(const uint32_t*)(smch + NSM_INHI + o1);
                ahi[mt][2] = *(const uint32_t*)(smch + NSM_INHI + o0 + 16);
                ahi[mt][3] = *(const uint32_t*)(smch + NSM_INHI + o1 + 16);
                alo[mt][0] = *(const uint32_t*)(smch + NSM_INLO + o0);
                alo[mt][1] = *(const uint32_t*)(smch + NSM_INLO + o1);
                alo[mt][2] = *(const uint32_t*)(smch + NSM_INLO + o0 + 16);
                alo[mt][3] = *(const uint32_t*)(smch + NSM_INLO + o1 + 16);
            }
#pragma unroll
            for (int nt = 0; nt < 4; nt++) {
                int n = ng * 32 + nt * 8 + lr;
                size_t ob = ((size_t)n * 136 + k0 + 2 * q) * 2;
                bhi[nt][0] = *(const uint32_t*)(smch + NSM_WHI + ob);
                bhi[nt][1] = *(const uint32_t*)(smch + NSM_WHI + ob + 16);
                blo[nt][0] = *(const uint32_t*)(smch + NSM_WLO + ob);
                blo[nt][1] = *(const uint32_t*)(smch + NSM_WLO + ob + 16);
            }
#pragma unroll
            for (int mt = 0; mt < 2; mt++) {
#pragma unroll
                for (int nt = 0; nt < 4; nt++) {
                    mma_bf16(acc[mt][nt], ahi[mt], bhi[nt]);
                    mma_bf16(acc[mt][nt], ahi[mt], blo[nt]);
                    mma_bf16(acc[mt][nt], alo[mt], bhi[nt]);
                }
            }
        }

#pragma unroll
        for (int mt = 0; mt < 2; mt++) {
#pragma unroll
            for (int half = 0; half < 2; half++) {
                int rr = mg * 32 + mt * 16 + lr + 8 * half;
                int m = m0 + rr;
                if (m < M) {
                    float* orow = out + (size_t)m * NB;
#pragma unroll
                    for (int nt = 0; nt < 4; nt++) {
                        int c = ng * 32 + nt * 8 + 2 * q;
                        float2 bv = *(const float2*)&sB[c];
                        *(float2*)(orow + c) = make_float2(acc[mt][nt][2 * half] + bv.x,
                                                           acc[mt][nt][2 * half + 1] + bv.y);
                    }
                }
            }
        }
        __syncthreads();
    }
}

// ---------------- fused f2out: x += ssp(agg@W1+b1)@W2+b2 ; zero agg ----------------
__global__ __launch_bounds__(512, 1) void hmma_f2out(
    const float* __restrict__ agg_in, const float* __restrict__ W1,
    const float* __restrict__ b1, const float* __restrict__ W2,
    const float* __restrict__ b2, float* __restrict__ x,
    float* __restrict__ aggz, int M, int ntiles)
{
    extern __shared__ char smch[];
    float* sB1 = (float*)(smch + N2_B1);
    float* sB2 = (float*)(smch + N2_B2);

    const int t = threadIdx.x;
    const int wid = t >> 5;
    const int lane = t & 31;
    const int q = lane & 3;
    const int lr = lane >> 2;

    if (t < 128) { sB1[t] = b1[t]; sB2[t] = b2[t]; }
#pragma unroll
    for (int i = 0; i < 8; i++) {
        int idx4 = i * 512 + t;
        int k = idx4 >> 5;
        int n0 = (idx4 & 31) * 4;
        float4 w1 = ((const float4*)W1)[idx4];
        float4 w2 = ((const float4*)W2)[idx4];
        float v1[4] = { w1.x, w1.y, w1.z, w1.w };
        float v2[4] = { w2.x, w2.y, w2.z, w2.w };
#pragma unroll
        for (int d = 0; d < 4; d++) {
            size_t off = ((size_t)(n0 + d) * 136 + k) * 2;
            __nv_bfloat16 hi, lo;
            bf16_split(v1[d], hi, lo);
            *(__nv_bfloat16*)(smch + N2_W1HI + off) = hi;
            *(__nv_bfloat16*)(smch + N2_W1LO + off) = lo;
            bf16_split(v2[d], hi, lo);
            *(__nv_bfloat16*)(smch + N2_W2HI + off) = hi;
            *(__nv_bfloat16*)(smch + N2_W2LO + off) = lo;
        }
    }
    __syncthreads();

    const int mg = wid & 3;
    const int ng = wid >> 2;

    for (int tile = blockIdx.x; tile < ntiles; tile += gridDim.x) {
        const int m0 = tile * 128;

        // stage agg tile (bf16 split)
        {
            int r = t >> 2, cq = (t & 3) * 32;
            const float4* src = (const float4*)(agg_in + (size_t)(m0 + r) * NB + cq);
            bool ok = (m0 + r < M);
#pragma unroll
            for (int j = 0; j < 8; j++) {
                float4 f = ok ? src[j] : make_float4(0.f, 0.f, 0.f, 0.f);
                __nv_bfloat162 h0, h1, l0, l1;
                bf16_split(f.x, h0.x, l0.x); bf16_split(f.y, h0.y, l0.y);
                bf16_split(f.z, h1.x, l1.x); bf16_split(f.w, h1.y, l1.y);
                size_t off = ((size_t)r * 136 + cq + j * 4) * 2;
                *(uint2*)(smch + N2_INHI + off) = make_uint2(*(uint32_t*)&h0, *(uint32_t*)&h1);
                *(uint2*)(smch + N2_INLO + off) = make_uint2(*(uint32_t*)&l0, *(uint32_t*)&l1);
            }
        }
        __syncthreads();

        // phase 1: C1 = agg @ W1
        float acc[2][4][4];
#pragma unroll
        for (int mt = 0; mt < 2; mt++)
#pragma unroll
            for (int nt = 0; nt < 4; nt++)
#pragma unroll
                for (int v = 0; v < 4; v++) acc[mt][nt][v] = 0.f;

#pragma unroll 2
        for (int ks = 0; ks < 8; ks++) {
            const int k0 = ks * 16;
            uint32_t ahi[2][4], alo[2][4], bhi[4][2], blo[4][2];
#pragma unroll
            for (int mt = 0; mt < 2; mt++) {
                int m = mg * 32 + mt * 16 + lr;
                size_t o0 = ((size_t)m * 136 + k0 + 2 * q) * 2;
                size_t o1 = ((size_t)(m + 8) * 136 + k0 + 2 * q) * 2;
                ahi[mt][0] = *(const uint32_t*)(smch + N2_INHI + o0);
                ahi[mt][1] = *(const uint32_t*)(smch + N2_INHI + o1);
                ahi[mt][2] = *(const uint32_t*)(smch + N2_INHI + o0 + 16);
                ahi[mt][3] = *(const uint32_t*)(smch + N2_INHI + o1 + 16);
                alo[mt][0] = *(const uint32_t*)(smch + N2_INLO + o0);
                alo[mt][1] = *(const uint32_t*)(smch + N2_INLO + o1);
                alo[mt][2] = *(const uint32_t*)(smch + N2_INLO + o0 + 16);
                alo[mt][3] = *(const uint32_t*)(smch + N2_INLO + o1 + 16);
            }
#pragma unroll
            for (int nt = 0; nt < 4; nt++) {
                int n = ng * 32 + nt * 8 + lr;
                size_t ob = ((size_t)n * 136 + k0 + 2 * q) * 2;
                bhi[nt][0] = *(const uint32_t*)(smch + N2_W1HI + ob);
                bhi[nt][1] = *(const uint32_t*)(smch + N2_W1HI + ob + 16);
                blo[nt][0] = *(const uint32_t*)(smch + N2_W1LO + ob);
                blo[nt][1] = *(const uint32_t*)(smch + N2_W1LO + ob + 16);
            }
#pragma unroll
            for (int mt = 0; mt < 2; mt++) {
#pragma unroll
                for (int nt = 0; nt < 4; nt++) {
                    mma_bf16(acc[mt][nt], ahi[mt], bhi[nt]);
                    mma_bf16(acc[mt][nt], ahi[mt], blo[nt]);
                    mma_bf16(acc[mt][nt], alo[mt], bhi[nt]);
                }
            }
        }
        __syncthreads();  // all phase-1 reads of IN done

        // H = ssp(C1 + b1) -> overwrite IN buffers (bf16 split)
#pragma unroll
        for (int mt = 0; mt < 2; mt++) {
#pragma unroll
            for (int half = 0; half < 2; half++) {
                int rr = mg * 32 + mt * 16 + lr + 8 * half;
#pragma unroll
                for (int nt = 0; nt < 4; nt++) {
                    int c = ng * 32 + nt * 8 + 2 * q;
                    float2 bv = *(const float2*)&sB1[c];
                    float h0 = sspf(acc[mt][nt][2 * half] + bv.x);
                    float h1 = sspf(acc[mt][nt][2 * half + 1] + bv.y);
                    __nv_bfloat162 hh, ll;
                    bf16_split(h0, hh.x, ll.x);
                    bf16_split(h1, hh.y, ll.y);
                    size_t off = ((size_t)rr * 136 + c) * 2;
                    *(uint32_t*)(smch + N2_INHI + off) = *(uint32_t*)&hh;
                    *(uint32_t*)(smch + N2_INLO + off) = *(uint32_t*)&ll;
                }
            }
        }
        __syncthreads();

        // phase 2: C2 = H @ W2
#pragma unroll
        for (int mt = 0; mt < 2; mt++)
#pragma unroll
            for (int nt = 0; nt < 4; nt++)
#pragma unroll
                for (int v = 0; v < 4; v++) acc[mt][nt][v] = 0.f;

#pragma unroll 2
        for (int ks = 0; ks < 8; ks++) {
            const int k0 = ks * 16;
            uint32_t ahi[2][4], alo[2][4], bhi[4][2], blo[4][2];
#pragma unroll
            for (int mt = 0; mt < 2; mt++) {
                int m = mg * 32 + mt * 16 + lr;
                size_t o0 = ((size_t)m * 136 + k0 + 2 * q) * 2;
                size_t o1 = ((size_t)(m + 8) * 136 + k0 + 2 * q) * 2;
                ahi[mt][0] = *(const uint32_t*)(smch + N2_INHI + o0);
                ahi[mt][1] = *(const uint32_t*)(smch + N2_INHI + o1);
                ahi[mt][2] = *(const uint32_t*)(smch + N2_INHI + o0 + 16);
                ahi[mt][3] = *(const uint32_t*)(smch + N2_INHI + o1 + 16);
                alo[mt][0] = *(const uint32_t*)(smch + N2_INLO + o0);
                alo[mt][1] = *(const uint32_t*)(smch + N2_INLO + o1);
                alo[mt][2] = *(const uint32_t*)(smch + N2_INLO + o0 + 16);
                alo[mt][3] = *(const uint32_t*)(smch + N2_INLO + o1 + 16);
            }
#pragma unroll
            for (int nt = 0; nt < 4; nt++) {
                int n = ng * 32 + nt * 8 + lr;
                size_t ob = ((size_t)n * 136 + k0 + 2 * q) * 2;
                bhi[nt][0] = *(const uint32_t*)(smch + N2_W2HI + ob);
                bhi[nt][1] = *(const uint32_t*)(smch + N2_W2HI + ob + 16);
                blo[nt][0] = *(const uint32_t*)(smch + N2_W2LO + ob);
                blo[nt][1] = *(const uint32_t*)(smch + N2_W2LO + ob + 16);
            }
#pragma unroll
            for (int mt = 0; mt < 2; mt++) {
#pragma unroll
                for (int nt = 0; nt < 4; nt++) {
                    mma_bf16(acc[mt][nt], ahi[mt], bhi[nt]);
                    mma_bf16(acc[mt][nt], ahi[mt], blo[nt]);
                    mma_bf16(acc[mt][nt], alo[mt], bhi[nt]);
                }
            }
        }

        // epilogue: x += C2 + b2 ; zero agg
#pragma unroll
        for (int mt = 0; mt < 2; mt++) {
#pragma unroll
            for (int half = 0; half < 2; half++) {
                int rr = mg * 32 + mt * 16 + lr + 8 * half;
                int m = m0 + rr;
                if (m < M) {
                    float* xrow = x + (size_t)m * NB;
                    float* zrow = aggz ? aggz + (size_t)m * NB : 0;
#pragma unroll
                    for (int nt = 0; nt < 4; nt++) {
                        int c = ng * 32 + nt * 8 + 2 * q;
                        float2 bv = *(const float2*)&sB2[c];
                        float2 xv = *(const float2*)(xrow + c);
                        *(float2*)(xrow + c) = make_float2(xv.x + acc[mt][nt][2 * half] + bv.x,
                                                           xv.y + acc[mt][nt][2 * half + 1] + bv.y);
                        if (aggz) *(float2*)(zrow + c) = make_float2(0.f, 0.f);
                    }
                }
            }
        }
        __syncthreads();
    }
}

// ---------------- persistent fused edge kernel (unchanged R8) ----------------
__global__ __launch_bounds__(512, 1) void edge_kernel(
    const int* __restrict__ ci, const int* __restrict__ cj,
    const float* __restrict__ W1, const float* __restrict__ b1,
    const float* __restrict__ W2, const float* __restrict__ b2,
    const float* __restrict__ Ff, const float* __restrict__ rcut,
    const float* __restrict__ xf, float* __restrict__ agg,
    const int* __restrict__ cntPtr)
{
    extern __shared__ char smch[];
    float* sB1 = (float*)(smch + SM_B1);
    float* sB2 = (float*)(smch + SM_B2);
    float* sRC = (float*)(smch + SM_RC);
    int*   sII = (int*)(smch + SM_II);
    int*   sJJ = (int*)(smch + SM_JJ);

    const int E = *cntPtr;
    const int ntiles = (E + 127) >> 7;

    const int t = threadIdx.x;
    const int wid = t >> 5;
    const int lane = t & 31;
    const int q = lane & 3;
    const int lr = lane >> 2;

    if (t < 128) { sB1[t] = b1[t]; sB2[t] = b2[t]; }
#pragma unroll
    for (int i = 0; i < 2; i++) {
        int idx4 = i * 512 + t;
        int k = idx4 >> 5;
        int n0 = (idx4 & 31) * 4;
        float4 w = ((const float4*)W1)[idx4];
        float vs[4] = { w.x, w.y, w.z, w.w };
#pragma unroll
        for (int d = 0; d < 4; d++) {
            __nv_bfloat16 hi, lo;
            bf16_split(vs[d], hi, lo);
            size_t off = ((size_t)(n0 + d) * 40 + k) * 2;
            *(__nv_bfloat16*)(smch + SM_W1HI + off) = hi;
            *(__nv_bfloat16*)(smch + SM_W1LO + off) = lo;
        }
    }
#pragma unroll
    for (int i = 0; i < 8; i++) {
        int idx4 = i * 512 + t;
        int k = idx4 >> 5;
        int n0 = (idx4 & 31) * 4;
        float4 w = ((const float4*)W2)[idx4];
        float vs[4] = { w.x, w.y, w.z, w.w };
#pragma unroll
        for (int d = 0; d < 4; d++) {
            __nv_bfloat16 hi, lo;
            bf16_split(vs[d], hi, lo);
            size_t off = ((size_t)(n0 + d) * 136 + k) * 2;
            *(__nv_bfloat16*)(smch + SM_WHI + off) = hi;
            *(__nv_bfloat16*)(smch + SM_WLO + off) = lo;
        }
    }

    for (int tile = blockIdx.x; tile < ntiles; tile += gridDim.x) {
        const int eb = tile * 128;

        {
            int r = t >> 2, kq = (t & 3) * 8;
            float4 f0 = make_float4(0.f, 0.f, 0.f, 0.f);
            float4 f1 = make_float4(0.f, 0.f, 0.f, 0.f);
            if (eb + r < E) {
                const float4* src = (const float4*)(Ff + (size_t)(eb + r) * NRBF + kq);
                f0 = src[0]; f1 = src[1];
            }
            __nv_bfloat162 h0, h1, h2, h3, l0, l1, l2, l3;
            bf16_split(f0.x, h0.x, l0.x); bf16_split(f0.y, h0.y, l0.y);
            bf16_split(f0.z, h1.x, l1.x); bf16_split(f0.w, h1.y, l1.y);
            bf16_split(f1.x, h2.x, l2.x); bf16_split(f1.y, h2.y, l2.y);
            bf16_split(f1.z, h3.x, l3.x); bf16_split(f1.w, h3.y, l3.y);
            size_t off = ((size_t)r * 40 + kq) * 2;
            uint4 uh = make_uint4(*(uint32_t*)&h0, *(uint32_t*)&h1, *(uint32_t*)&h2, *(uint32_t*)&h3);
            uint4 ul = make_uint4(*(uint32_t*)&l0, *(uint32_t*)&l1, *(uint32_t*)&l2, *(uint32_t*)&l3);
            *(uint4*)(smch + SM_FHI + off) = uh;
            *(uint4*)(smch + SM_FLO + off) = ul;
        }
        if (t < 128) {
            int e = eb + t;
            float rcv = 0.f; int iiv = 0, jjv = 0;
            if (e < E) { rcv = rcut[e]; iiv = ci[e]; jjv = cj[e]; }
            sRC[t] = rcv; sII[t] = iiv; sJJ[t] = jjv;
        }
        __syncthreads();

        {
            const int pm = wid & 7, pn = wid >> 3;
            const int m0 = pm * 16, n0 = pn * 64;
            uint32_t ahi[2][4], alo[2][4];
#pragma unroll
            for (int ks = 0; ks < 2; ks++) {
                size_t o0 = ((size_t)(m0 + lr) * 40 + ks * 16 + 2 * q) * 2;
                size_t o1 = o0 + 640;
                ahi[ks][0] = *(const uint32_t*)(smch + SM_FHI + o0);
                ahi[ks][1] = *(const uint32_t*)(smch + SM_FHI + o1);
                ahi[ks][2] = *(const uint32_t*)(smch + SM_FHI + o0 + 16);
                ahi[ks][3] = *(const uint32_t*)(smch + SM_FHI + o1 + 16);
                alo[ks][0] = *(const uint32_t*)(smch + SM_FLO + o0);
                alo[ks][1] = *(const uint32_t*)(smch + SM_FLO + o1);
                alo[ks][2] = *(const uint32_t*)(smch + SM_FLO + o0 + 16);
                alo[ks][3] = *(const uint32_t*)(smch + SM_FLO + o1 + 16);
            }
#pragma unroll
            for (int nt = 0; nt < 8; nt++) {
                int n = n0 + nt * 8 + lr;
                float c[4] = { 0.f, 0.f, 0.f, 0.f };
#pragma unroll
                for (int ks = 0; ks < 2; ks++) {
                    size_t ob = ((size_t)n * 40 + ks * 16 + 2 * q) * 2;
                    uint32_t bh[2] = { *(const uint32_t*)(smch + SM_W1HI + ob),
                                       *(const uint32_t*)(smch + SM_W1HI + ob + 16) };
                    uint32_t bl[2] = { *(const uint32_t*)(smch + SM_W1LO + ob),
                                       *(const uint32_t*)(smch + SM_W1LO + ob + 16) };
                    mma_bf16(c, ahi[ks], bh);
                    mma_bf16(c, ahi[ks], bl);
                    mma_bf16(c, alo[ks], bh);
                }
                int cc = n0 + nt * 8 + 2 * q;
                float2 bv = *(const float2*)&sB1[cc];
                float h00 = sspf(c[0] + bv.x), h01 = sspf(c[1] + bv.y);
                float h10 = sspf(c[2] + bv.x), h11 = sspf(c[3] + bv.y);
                __nv_bfloat162 p0, p1, e0, e1;
                bf16_split(h00, p0.x, e0.x); bf16_split(h01, p0.y, e0.y);
                bf16_split(h10, p1.x, e1.x); bf16_split(h11, p1.y, e1.y);
                size_t oh0 = ((size_t)(m0 + lr) * 136 + cc) * 2;
                size_t oh1 = oh0 + 136 * 8 * 2;
                *(uint32_t*)(smch + SM_HHI + oh0) = *(uint32_t*)&p0;
                *(uint32_t*)(smch + SM_HHI + oh1) = *(uint32_t*)&p1;
                *(uint32_t*)(smch + SM_HLO + oh0) = *(uint32_t*)&e0;
                *(uint32_t*)(smch + SM_HLO + oh1) = *(uint32_t*)&e1;
            }
        }
        __syncthreads();

        {
            const int mg = wid & 3;
            const int ng = wid >> 2;

            float acc[2][4][4];
#pragma unroll
            for (int mt = 0; mt < 2; mt++)
#pragma unroll
                for (int nt = 0; nt < 4; nt++)
#pragma unroll
                    for (int v = 0; v < 4; v++) acc[mt][nt][v] = 0.f;

#pragma unroll 2
            for (int ks = 0; ks < 8; ks++) {
                const int k0 = ks * 16;
                uint32_t ahi[2][4], alo[2][4], bhi[4][2], blo[4][2];
#pragma unroll
                for (int mt = 0; mt < 2; mt++) {
                    int m = mg * 32 + mt * 16 + lr;
                    size_t o0 = ((size_t)m * 136 + k0 + 2 * q) * 2;
                    size_t o1 = ((size_t)(m + 8) * 136 + k0 + 2 * q) * 2;
                    ahi[mt][0] = *(const uint32_t*)(smch + SM_HHI + o0);
                    ahi[mt][1] = *(const uint32_t*)(smch + SM_HHI + o1);
                    ahi[mt][2] = *(const uint32_t*)(smch + SM_HHI + o0 + 16);
                    ahi[mt][3] = *(const uint32_t*)(smch + SM_HHI + o1 + 16);
                    alo[mt][0] = *(const uint32_t*)(smch + SM_HLO + o0);
                    alo[mt][1] = *(const uint32_t*)(smch + SM_HLO + o1);
                    alo[mt][2] = *(const uint32_t*)(smch + SM_HLO + o0 + 16);
                    alo[mt][3] = *(const uint32_t*)(smch + SM_HLO + o1 + 16);
                }
#pragma unroll
                for (int nt = 0; nt < 4; nt++) {
                    int n = ng * 32 + nt * 8 + lr;
                    size_t ob = ((size_t)n * 136 + k0 + 2 * q) * 2;
                    bhi[nt][0] = *(const uint32_t*)(smch + SM_WHI + ob);
                    bhi[nt][1] = *(const uint32_t*)(smch + SM_WHI + ob + 16);
                    blo[nt][0] = *(const uint32_t*)(smch + SM_WLO + ob);
                    blo[nt][1] = *(const uint32_t*)(smch + SM_WLO + ob + 16);
                }
#pragma unroll
                for (int mt = 0; mt < 2; mt++) {
#pragma unroll
                    for (int nt = 0; nt < 4; nt++) {
                        mma_bf16(acc[mt][nt], ahi[mt], bhi[nt]);
                        mma_bf16(acc[mt][nt], ahi[mt], blo[nt]);
                        mma_bf16(acc[mt][nt], alo[mt], bhi[nt]);
                    }
                }
            }

#pragma unroll
            for (int mt = 0; mt < 2; mt++) {
#pragma unroll
                for (int half = 0; half < 2; half++) {
                    int r = mg * 32 + mt * 16 + lr + 8 * half;
                    float rc = sRC[r];
                    int ii = sII[r], jj = sJJ[r];
                    const float* xrow = xf + (size_t)jj * NB;
                    float* arow = agg + (size_t)ii * NB;
#pragma unroll
                    for (int nt = 0; nt < 4; nt++) {
                        int c = ng * 32 + nt * 8 + 2 * q;
                        float2 xv = *(const float2*)(xrow + c);
                        float2 bv = *(const float2*)&sB2[c];
                        float v0 = (acc[mt][nt][2 * half]     + bv.x) * rc * xv.x;
                        float v1 = (acc[mt][nt][2 * half + 1] + bv.y) * rc * xv.y;
                        red_add_v2(arow + c, v0, v1);
                    }
                }
            }
        }
        __syncthreads();
    }
}

// ---------------- head ----------------
__global__ void head_final(const float* __restrict__ h, const float* __restrict__ w2,
                           const int* __restrict__ batch, float* __restrict__ out, int M) {
    int w = (blockIdx.x * blockDim.x + threadIdx.x) >> 5;
    int lane = threadIdx.x & 31;
    if (w >= M) return;
    float4 v = ((const float4*)(h + (size_t)w * NB))[lane];
    float4 ww = ((const float4*)w2)[lane];
    float s = siluf(v.x) * ww.x + siluf(v.y) * ww.y + siluf(v.z) * ww.z + siluf(v.w) * ww.w;
#pragma unroll
    for (int o2 = 16; o2 > 0; o2 >>= 1) s += __shfl_xor_sync(0xffffffffu, s, o2);
    if (lane == 0) atomicAdd(&out[batch[w]], s);
}

// ---------------- launch ----------------
typedef void (*ngemm_fn)(const float*, const float*, const float*, float*, int, int);

extern "C" void kernel_launch(void* const* d_in, const int* in_sizes, int n_in,
                              void* d_out, int out_size)
{
    const int*   z         = (const int*)d_in[0];
    const int*   z_res     = (const int*)d_in[1];
    const float* pos       = (const float*)d_in[2];
    const int*   idx_i     = (const int*)d_in[3];
    const int*   idx_j     = (const int*)d_in[4];
    const int*   edge_attr = (const int*)d_in[5];
    const int*   batch     = (const int*)d_in[6];
    const float* ele_emb   = (const float*)d_in[7];
    const float* res_emb   = (const float*)d_in[8];
    const float* edge_emb  = (const float*)d_in[9];
    const float* in2f_W    = (const float*)d_in[10];
    const float* filt_W1   = (const float*)d_in[11];
    const float* filt_b1   = (const float*)d_in[12];
    const float* filt_W2   = (const float*)d_in[13];
    const float* filt_b2   = (const float*)d_in[14];
    const float* f2out_W1  = (const float*)d_in[15];
    const float* f2out_b1  = (const float*)d_in[16];
    const float* f2out_W2  = (const float*)d_in[17];
    const float* f2out_b2  = (const float*)d_in[18];
    const float* head_W1   = (const float*)d_in[19];
    const float* head_b1   = (const float*)d_in[20];
    const float* head_W2   = (const float*)d_in[21];
    float* out = (float*)d_out;

    const int N = in_sizes[0];
    const int E = in_sizes[3];

    int *pCnt, *pCi, *pCj;
    float *pRc, *pF, *pX, *pXf, *pAgg;
    cudaGetSymbolAddress((void**)&pCnt, g_cnt);
    cudaGetSymbolAddress((void**)&pCi, g_ci);
    cudaGetSymbolAddress((void**)&pCj, g_cj);
    cudaGetSymbolAddress((void**)&pRc, g_rc);
    cudaGetSymbolAddress((void**)&pF, g_F);
    cudaGetSymbolAddress((void**)&pX, g_x);
    cudaGetSymbolAddress((void**)&pXf, g_xf);
    cudaGetSymbolAddress((void**)&pAgg, g_agg);

    ngemm_fn f_plain = hmma_node_gemm<0>;
    ngemm_fn f_head  = hmma_node_gemm<2>;

    cudaFuncSetAttribute((const void*)f_plain, cudaFuncAttributeMaxDynamicSharedMemorySize, NODE_SMEM_BYTES);
    cudaFuncSetAttribute((const void*)f_head,  cudaFuncAttributeMaxDynamicSharedMemorySize, NODE_SMEM_BYTES);
    cudaFuncSetAttribute((const void*)hmma_f2out, cudaFuncAttributeMaxDynamicSharedMemorySize, NODE2_SMEM_BYTES);
    cudaFuncSetAttribute((const void*)edge_kernel, cudaFuncAttributeMaxDynamicSharedMemorySize, EDGE_SMEM_BYTES);

    int nsm = 148;
    cudaDeviceGetAttribute(&nsm, cudaDevAttrMultiProcessorCount, 0);
    const int ntiles = (N + 127) / 128;

    prep_zero<<<1, 32>>>();
    edge_compact<<<(E + 255) / 256, 256>>>(pos, idx_i, idx_j, edge_attr, edge_emb, E);
    embed_zero<<<(N * NB + 255) / 256, 256>>>(z, z_res, ele_emb, res_emb, pX, pAgg, out, N, out_size);

    for (int it = 0; it < 6; it++) {
        f_plain<<<nsm, 512, NODE_SMEM_BYTES>>>(
            pX, in2f_W + (size_t)it * NB * NB, nullptr, pXf, N, ntiles);
        edge_kernel<<<nsm, 512, EDGE_SMEM_BYTES>>>(
            pCi, pCj,
            filt_W1 + (size_t)it * NRBF * NB, filt_b1 + (size_t)it * NB,
            filt_W2 + (size_t)it * NB * NB,  filt_b2 + (size_t)it * NB,
            pF, pRc, pXf, pAgg, pCnt);
        hmma_f2out<<<nsm, 512, NODE2_SMEM_BYTES>>>(
            pAgg, f2out_W1 + (size_t)it * NB * NB, f2out_b1 + (size_t)it * NB,
            f2out_W2 + (size_t)it * NB * NB, f2out_b2 + (size_t)it * NB,
            pX, (it < 5) ? pAgg : nullptr, N, ntiles);
    }

    f_head<<<nsm, 512, NODE_SMEM_BYTES>>>(pX, head_W1, head_b1, pXf, N, ntiles);
    head_final<<<(N + 7) / 8, 256>>>(pXf, head_W2, batch, out, N);
}